// round 12
// baseline (speedup 1.0000x reference)
#include <cuda_runtime.h>
#include <cuda_bf16.h>
#include <math.h>
#include <stdint.h>

#define SQ   2048
#define D    1024
#define NH   16
#define DK   64
#define DFF  4096

// ================= PTX helpers (baseline ISA only) ==========================
__device__ __forceinline__ uint32_t smem_u32(const void* p) {
    uint32_t a;
    asm("{ .reg .u64 t; cvta.to.shared.u64 t, %1; cvt.u32.u64 %0, t; }" : "=r"(a) : "l"(p));
    return a;
}
__device__ __forceinline__ void cpa16(uint32_t dst, const void* src) {
    asm volatile("cp.async.cg.shared.global [%0], [%1], 16;" :: "r"(dst), "l"(src));
}
#define CPA_COMMIT() asm volatile("cp.async.commit_group;" ::: "memory")
__device__ __forceinline__ void ldm_x4(uint32_t& r0, uint32_t& r1, uint32_t& r2, uint32_t& r3, uint32_t addr) {
    asm volatile("ldmatrix.sync.aligned.m8n8.x4.shared.b16 {%0,%1,%2,%3}, [%4];"
                 : "=r"(r0), "=r"(r1), "=r"(r2), "=r"(r3) : "r"(addr));
}
__device__ __forceinline__ void ldm_x2(uint32_t& r0, uint32_t& r1, uint32_t addr) {
    asm volatile("ldmatrix.sync.aligned.m8n8.x2.shared.b16 {%0,%1}, [%2];"
                 : "=r"(r0), "=r"(r1) : "r"(addr));
}
__device__ __forceinline__ void ldm_x2t(uint32_t& r0, uint32_t& r1, uint32_t addr) {
    asm volatile("ldmatrix.sync.aligned.m8n8.x2.trans.shared.b16 {%0,%1}, [%2];"
                 : "=r"(r0), "=r"(r1) : "r"(addr));
}
__device__ __forceinline__ void mma_bf16(float* c, uint32_t a0, uint32_t a1, uint32_t a2, uint32_t a3,
                                         uint32_t b0, uint32_t b1) {
    asm volatile("mma.sync.aligned.m16n8k16.row.col.f32.bf16.bf16.f32 "
                 "{%0,%1,%2,%3}, {%4,%5,%6,%7}, {%8,%9}, {%0,%1,%2,%3};"
                 : "+f"(c[0]), "+f"(c[1]), "+f"(c[2]), "+f"(c[3])
                 : "r"(a0), "r"(a1), "r"(a2), "r"(a3), "r"(b0), "r"(b1));
}
__device__ __forceinline__ float wred_max(float v) {
#pragma unroll
    for (int o = 16; o > 0; o >>= 1) v = fmaxf(v, __shfl_xor_sync(0xffffffffu, v, o));
    return v;
}
__device__ __forceinline__ float wred_sum(float v) {
#pragma unroll
    for (int o = 16; o > 0; o >>= 1) v += __shfl_xor_sync(0xffffffffu, v, o);
    return v;
}

// ================= scratch =================
__device__ __nv_bfloat16 g_nx_h[SQ * D],  g_nx_l[SQ * D];
__device__ __nv_bfloat16 g_h_h[SQ * D],   g_h_l[SQ * D];
__device__ __nv_bfloat16 g_qkv_h[SQ * 3 * D], g_qkv_l[SQ * 3 * D];
__device__ __nv_bfloat16 g_ctx_h[SQ * D], g_ctx_l[SQ * D];
__device__ float         g_p1[SQ * D];
__device__ float         g_n2[SQ * D];
__device__ __nv_bfloat16 g_n2_h[SQ * D],  g_n2_l[SQ * D];
__device__ __nv_bfloat16 g_ff1_h[SQ * DFF], g_ff1_l[SQ * DFF];
__device__ float         g_attn_scratch[(size_t)NH * SQ * SQ];
__device__ __nv_bfloat16 g_attn_h[(size_t)NH * SQ * SQ];
__device__ __nv_bfloat16 g_attn_l[(size_t)NH * SQ * SQ];
// transposed/split weights [N, K]
__device__ __nv_bfloat16 g_wint_h[D * D],      g_wint_l[D * D];
__device__ __nv_bfloat16 g_wqkvt_h[3 * D * D], g_wqkvt_l[3 * D * D];
__device__ __nv_bfloat16 g_w2t_h[D * D],       g_w2t_l[D * D];
__device__ __nv_bfloat16 g_wf1t_h[DFF * D],    g_wf1t_l[DFF * D];
__device__ __nv_bfloat16 g_wf2t_h[D * DFF],    g_wf2t_l[D * DFF];
// Wo*W2 fold
__device__ __nv_bfloat16 g_wo_nt_h[D * D],     g_wo_nt_l[D * D];   // Wo straight split [a, mid]
__device__ __nv_bfloat16 g_comb_h[D * D],      g_comb_l[D * D];    // comb[b, a] = (Wo@W2)[a, b]
__device__ float         g_bcomb[D];
__device__ float         g_zero[D];   // zero-initialized, never written
__device__ float         g_bqkv[3 * D];

// ================= batched weight prep ======================================
__device__ __forceinline__ void wprep_tile(
    const float* __restrict__ W, __nv_bfloat16* __restrict__ Th,
    __nv_bfloat16* __restrict__ Tl, int K, int N, int rowoff, int n0, int k0)
{
    __shared__ float t[32][33];
    const int tx = threadIdx.x, ty = threadIdx.y;
    for (int i = ty; i < 32; i += 8)
        t[i][tx] = W[(size_t)(k0 + i) * N + n0 + tx];
    __syncthreads();
    for (int i = ty; i < 32; i += 8) {
        float v = t[tx][i];
        __nv_bfloat16 h = __float2bfloat16_rn(v);
        size_t o = (size_t)(rowoff + n0 + i) * K + k0 + tx;
        Th[o] = h;
        Tl[o] = __float2bfloat16_rn(v - __bfloat162float(h));
    }
}

// z: 0 W_in, 1 Wq, 2 Wk, 3 Wv, 4 W2 (all transposed) ; 5 Wo straight split.
__global__ __launch_bounds__(256) void wprep_dd(
    const float* __restrict__ W_in, const float* __restrict__ Wq,
    const float* __restrict__ Wk,   const float* __restrict__ Wv,
    const float* __restrict__ Wo,   const float* __restrict__ W2,
    const float* __restrict__ bq,   const float* __restrict__ bk,
    const float* __restrict__ bv,
    __nv_bfloat16* winth, __nv_bfloat16* wintl,
    __nv_bfloat16* wqkvth, __nv_bfloat16* wqkvtl,
    __nv_bfloat16* wonth, __nv_bfloat16* wontl,
    __nv_bfloat16* w2th, __nv_bfloat16* w2tl, float* bqkv)
{
    const int z = blockIdx.z;
    if (z == 5) {
        // straight hi/lo split of Wo [D, D] (row-major, no transpose)
        const int col = blockIdx.x * 32 + threadIdx.x;
        for (int i = threadIdx.y; i < 32; i += 8) {
            const int row = blockIdx.y * 32 + i;
            float v = Wo[(size_t)row * D + col];
            __nv_bfloat16 h = __float2bfloat16_rn(v);
            size_t o = (size_t)row * D + col;
            wonth[o] = h;
            wontl[o] = __float2bfloat16_rn(v - __bfloat162float(h));
        }
        return;
    }
    const float* W; __nv_bfloat16 *Th, *Tl; int rowoff = 0;
    switch (z) {
        case 0:  W = W_in; Th = winth;  Tl = wintl;  break;
        case 1:  W = Wq;   Th = wqkvth; Tl = wqkvtl; rowoff = 0;     break;
        case 2:  W = Wk;   Th = wqkvth; Tl = wqkvtl; rowoff = D;     break;
        case 3:  W = Wv;   Th = wqkvth; Tl = wqkvtl; rowoff = 2 * D; break;
        default: W = W2;   Th = w2th;   Tl = w2tl;   break;   // z == 4
    }
    wprep_tile(W, Th, Tl, D, D, rowoff, blockIdx.x * 32, blockIdx.y * 32);
    if (z >= 1 && z <= 3 && blockIdx.x == 0 && blockIdx.y == 0) {
        const float* b = (z == 1) ? bq : (z == 2) ? bk : bv;
        for (int j = threadIdx.y * 32 + threadIdx.x; j < D; j += 256)
            bqkv[(z - 1) * D + j] = b[j];
    }
}

__global__ __launch_bounds__(256) void wprep_ff(
    const float* __restrict__ Wf1, const float* __restrict__ Wf2,
    __nv_bfloat16* f1h, __nv_bfloat16* f1l,
    __nv_bfloat16* f2h, __nv_bfloat16* f2l)
{
    const int z = blockIdx.z;
    if (z == 0)
        wprep_tile(Wf1, f1h, f1l, D, DFF, 0, blockIdx.x * 32, blockIdx.y * 32);
    else
        wprep_tile(Wf2, f2h, f2l, DFF, D, 0, blockIdx.y * 32, blockIdx.x * 32);
}

// b_comb[n] = sum_k bo[k] * W2[k, n] + b2[n]
__global__ __launch_bounds__(256) void bias_fold(
    const float* __restrict__ bo, const float* __restrict__ W2,
    const float* __restrict__ b2, float* __restrict__ bcomb)
{
    const int n = blockIdx.x * 256 + threadIdx.x;
    float s = b2[n];
#pragma unroll 4
    for (int k = 0; k < D; k++) s += bo[k] * W2[(size_t)k * D + n];
    bcomb[n] = s;
}

// ================= LayerNorm (warp-shuffle reductions) ======================
template<int WF32, int WSPLIT>
__global__ __launch_bounds__(256) void ln_kernel(
    const float* __restrict__ x, const float* __restrict__ g,
    const float* __restrict__ b, float* __restrict__ outf,
    __nv_bfloat16* __restrict__ oh, __nv_bfloat16* __restrict__ ol)
{
    __shared__ float red[8];
    __shared__ float bc[2];
    const int row = blockIdx.x;
    const int tid = threadIdx.x;
    const int lane = tid & 31, warp = tid >> 5;
    float4 v = *(const float4*)(x + (size_t)row * D + tid * 4);

    float s = wred_sum(v.x + v.y + v.z + v.w);
    if (lane == 0) red[warp] = s;
    __syncthreads();
    if (warp == 0) {
        float t = red[lane & 7];
        t += __shfl_xor_sync(0xffffffffu, t, 1);
        t += __shfl_xor_sync(0xffffffffu, t, 2);
        t += __shfl_xor_sync(0xffffffffu, t, 4);
        if (lane == 0) bc[0] = t;
    }
    __syncthreads();
    const float mean = bc[0] * (1.0f / D);
    const float dx = v.x - mean, dy = v.y - mean, dz = v.z - mean, dw = v.w - mean;

    float s2 = wred_sum(dx * dx + dy * dy + dz * dz + dw * dw);
    if (lane == 0) red[warp] = s2;
    __syncthreads();
    if (warp == 0) {
        float t = red[lane & 7];
        t += __shfl_xor_sync(0xffffffffu, t, 1);
        t += __shfl_xor_sync(0xffffffffu, t, 2);
        t += __shfl_xor_sync(0xffffffffu, t, 4);
        if (lane == 0) bc[1] = t;
    }
    __syncthreads();
    const float inv = 1.0f / (sqrtf(bc[1] * (1.0f / D)) + 1e-6f);

    float4 gg = *(const float4*)(g + tid * 4);
    float4 bb = *(const float4*)(b + tid * 4);
    float o0 = gg.x * dx * inv + bb.x;
    float o1 = gg.y * dy * inv + bb.y;
    float o2 = gg.z * dz * inv + bb.z;
    float o3 = gg.w * dw * inv + bb.w;
    const size_t base = (size_t)row * D + tid * 4;
    if (WF32) {
        float4 o4 = {o0, o1, o2, o3};
        *(float4*)(outf + base) = o4;
    }
    if (WSPLIT) {
        float vv[4] = {o0, o1, o2, o3};
        __nv_bfloat16 hs[4], ls[4];
#pragma unroll
        for (int i = 0; i < 4; i++) {
            hs[i] = __float2bfloat16_rn(vv[i]);
            ls[i] = __float2bfloat16_rn(vv[i] - __bfloat162float(hs[i]));
        }
        *(uint2*)(oh + base) = *(uint2*)hs;
        *(uint2*)(ol + base) = *(uint2*)ls;
    }
}

// ================= shared GEMM plumbing ======================================
__device__ __forceinline__ uint32_t swz(int row, int kb) {
    return (uint32_t)(row * 64 + ((kb ^ ((row >> 1) & 3)) << 4));
}

template<int ROWS>
__device__ __forceinline__ void load_tileT(
    const __nv_bfloat16* __restrict__ g, int ld, int row0, int k0, uint32_t sbase, int tid)
{
#pragma unroll
    for (int it = 0; it < ROWS / 64; it++) {
        int c = tid + (it << 8);
        int row = c >> 2, kb = c & 3;
        cpa16(sbase + swz(row, kb), g + (size_t)(row0 + row) * ld + k0 + kb * 8);
    }
}

// ================= mma.sync GEMM (2-stage, occ 2): C = A[M,K] @ T[N,K]^T =====
template<int BN, int WF32, int WSPLIT, int RELU, int RESID>
__global__ __launch_bounds__(256, 2) void mma_gemm(
    const __nv_bfloat16* __restrict__ Ah, const __nv_bfloat16* __restrict__ Al,
    const __nv_bfloat16* __restrict__ Bh, const __nv_bfloat16* __restrict__ Bl,
    const float* __restrict__ bias, const float* __restrict__ res,
    float* __restrict__ Cf, __nv_bfloat16* __restrict__ Chi, __nv_bfloat16* __restrict__ Clo,
    int N, int K)
{
    constexpr int MT   = (BN == 128) ? 4 : 2;
    constexpr int BB   = BN * 64;
    constexpr int SA_H = 0, SA_L = 8192, SB_H = 16384;
    constexpr int SB_L = 16384 + BB;
    constexpr int SSZ  = 16384 + 2 * BB;

    extern __shared__ char smem[];
    const uint32_t sb = smem_u32(smem);
    const int tid = threadIdx.x, wid = tid >> 5, lane = tid & 31;
    const int warp_m = (BN == 128) ? (wid & 1) : (wid & 3);
    const int warp_n = (BN == 128) ? (wid >> 1) : (wid >> 2);
    const int brow = blockIdx.y * 128, bcol = blockIdx.x * BN;

    float acc[MT][4][4];
#pragma unroll
    for (int a = 0; a < MT; a++)
#pragma unroll
        for (int b = 0; b < 4; b++)
#pragma unroll
            for (int c = 0; c < 4; c++) acc[a][b][c] = 0.0f;

    const int nch = K >> 5;
    load_tileT<128>(Ah, K, brow, 0, sb + SA_H, tid);
    load_tileT<128>(Al, K, brow, 0, sb + SA_L, tid);
    load_tileT<BN>(Bh, K, bcol, 0, sb + SB_H, tid);
    load_tileT<BN>(Bl, K, bcol, 0, sb + SB_L, tid);
    CPA_COMMIT();

    const int tileA = lane >> 3;
    const int rinA  = (lane & 7) + ((tileA & 1) << 3);
    const int kbA   = tileA >> 1;
    const int i16   = lane & 15;
    const int rinB  = i16 & 7;
    const int kbB   = i16 >> 3;

    for (int i = 0; i < nch; i++) {
        if (i + 1 < nch) {
            const uint32_t st = sb + ((i + 1) & 1) * SSZ;
            const int k0 = (i + 1) << 5;
            load_tileT<128>(Ah, K, brow, k0, st + SA_H, tid);
            load_tileT<128>(Al, K, brow, k0, st + SA_L, tid);
            load_tileT<BN>(Bh, K, bcol, k0, st + SB_H, tid);
            load_tileT<BN>(Bl, K, bcol, k0, st + SB_L, tid);
            CPA_COMMIT();
            asm volatile("cp.async.wait_group 1;" ::: "memory");
        } else {
            asm volatile("cp.async.wait_group 0;" ::: "memory");
        }
        __syncthreads();

        const uint32_t st = sb + (i & 1) * SSZ;
#pragma unroll
        for (int ks = 0; ks < 2; ks++) {
            uint32_t bh[4][2], bl[4][2];
#pragma unroll
            for (int nt = 0; nt < 4; nt++) {
                const int rowb = warp_n * 32 + nt * 8 + rinB;
                const uint32_t off = swz(rowb, (ks << 1) + kbB);
                ldm_x2(bh[nt][0], bh[nt][1], st + SB_H + off);
                ldm_x2(bl[nt][0], bl[nt][1], st + SB_L + off);
            }
#pragma unroll
            for (int mt = 0; mt < MT; mt++) {
                const int rowa = warp_m * (MT * 16) + mt * 16 + rinA;
                const uint32_t off = swz(rowa, (ks << 1) + kbA);
                uint32_t a0, a1, a2, a3, l0, l1, l2, l3;
                ldm_x4(a0, a1, a2, a3, st + SA_H + off);
                ldm_x4(l0, l1, l2, l3, st + SA_L + off);
#pragma unroll
                for (int nt = 0; nt < 4; nt++) {
                    mma_bf16(acc[mt][nt], a0, a1, a2, a3, bh[nt][0], bh[nt][1]);
                    mma_bf16(acc[mt][nt], a0, a1, a2, a3, bl[nt][0], bl[nt][1]);
                    mma_bf16(acc[mt][nt], l0, l1, l2, l3, bh[nt][0], bh[nt][1]);
                }
            }
        }
        __syncthreads();
    }

    const int g4 = lane >> 2, t4 = lane & 3;
#pragma unroll
    for (int mt = 0; mt < MT; mt++) {
#pragma unroll
        for (int half = 0; half < 2; half++) {
            const int row = brow + warp_m * (MT * 16) + mt * 16 + g4 + half * 8;
#pragma unroll
            for (int nt = 0; nt < 4; nt++) {
                const int col = bcol + warp_n * 32 + nt * 8 + t4 * 2;
                float v0 = acc[mt][nt][half * 2 + 0] + bias[col];
                float v1 = acc[mt][nt][half * 2 + 1] + bias[col + 1];
                if (RELU) { v0 = fmaxf(v0, 0.0f); v1 = fmaxf(v1, 0.0f); }
                const size_t o = (size_t)row * N + col;
                if (RESID) { v0 += res[o]; v1 += res[o + 1]; }
                if (WF32) {
                    float2 f2 = {v0, v1};
                    *(float2*)(Cf + o) = f2;
                }
                if (WSPLIT) {
                    __nv_bfloat16 h0 = __float2bfloat16_rn(v0);
                    __nv_bfloat16 h1 = __float2bfloat16_rn(v1);
                    __nv_bfloat16 q0 = __float2bfloat16_rn(v0 - __bfloat162float(h0));
                    __nv_bfloat16 q1 = __float2bfloat16_rn(v1 - __bfloat162float(h1));
                    __nv_bfloat162 hp = {h0, h1}, lp = {q0, q1};
                    *(__nv_bfloat162*)(Chi + o) = hp;
                    *(__nv_bfloat162*)(Clo + o) = lp;
                }
            }
        }
    }
}

#define GSMEM_128 (2 * 32768)
#define GSMEM_64  (2 * 24576)

// ================= score mma: S = (Q K^T)/8, causal ==========================
#define STG_A_H 0
#define STG_A_L 8192
#define STG_B_H 16384
#define STG_B_L 24576
#define STG_SZ  32768
#define SCORE_SMEM (2 * STG_SZ)

__global__ __launch_bounds__(256, 2) void score_mma(
    const __nv_bfloat16* __restrict__ qh, const __nv_bfloat16* __restrict__ ql,
    const __nv_bfloat16* __restrict__ kh, const __nv_bfloat16* __restrict__ kl,
    float* __restrict__ attn)
{
    const int brow = blockIdx.y * 128, bcol = blockIdx.x * 128;
    if (bcol >= brow + 128) return;
    const int h = blockIdx.z;
    const __nv_bfloat16* Ah = qh + h * DK;
    const __nv_bfloat16* Al = ql + h * DK;
    const __nv_bfloat16* Bh = kh + h * DK;
    const __nv_bfloat16* Bl = kl + h * DK;

    extern __shared__ char smem[];
    const uint32_t sb = smem_u32(smem);
    const int tid = threadIdx.x, wid = tid >> 5, lane = tid & 31;
    const int warp_m = wid & 1, warp_n = wid >> 1;

    float acc[4][4][4];
#pragma unroll
    for (int a = 0; a < 4; a++)
#pragma unroll
        for (int b = 0; b < 4; b++)
#pragma unroll
            for (int c = 0; c < 4; c++) acc[a][b][c] = 0.0f;

    load_tileT<128>(Ah, 3 * D, brow, 0, sb + STG_A_H, tid);
    load_tileT<128>(Al, 3 * D, brow, 0, sb + STG_A_L, tid);
    load_tileT<128>(Bh, 3 * D, bcol, 0, sb + STG_B_H, tid);
    load_tileT<128>(Bl, 3 * D, bcol, 0, sb + STG_B_L, tid);
    CPA_COMMIT();

    const int tileA = lane >> 3;
    const int rinA  = (lane & 7) + ((tileA & 1) << 3);
    const int kbA   = tileA >> 1;
    const int i16   = lane & 15;
    const int rinB  = i16 & 7;
    const int kbB   = i16 >> 3;

    for (int i = 0; i < 2; i++) {
        if (i == 0) {
            const uint32_t st = sb + STG_SZ;
            load_tileT<128>(Ah, 3 * D, brow, 32, st + STG_A_H, tid);
            load_tileT<128>(Al, 3 * D, brow, 32, st + STG_A_L, tid);
            load_tileT<128>(Bh, 3 * D, bcol, 32, st + STG_B_H, tid);
            load_tileT<128>(Bl, 3 * D, bcol, 32, st + STG_B_L, tid);
            CPA_COMMIT();
            asm volatile("cp.async.wait_group 1;" ::: "memory");
        } else {
            asm volatile("cp.async.wait_group 0;" ::: "memory");
        }
        __syncthreads();

        const uint32_t st = sb + (i & 1) * STG_SZ;
#pragma unroll
        for (int ks = 0; ks < 2; ks++) {
            uint32_t bh[4][2], bl[4][2];
#pragma unroll
            for (int nt = 0; nt < 4; nt++) {
                const int rowb = warp_n * 32 + nt * 8 + rinB;
                const uint32_t off = swz(rowb, (ks << 1) + kbB);
                ldm_x2(bh[nt][0], bh[nt][1], st + STG_B_H + off);
                ldm_x2(bl[nt][0], bl[nt][1], st + STG_B_L + off);
            }
#pragma unroll
            for (int mt = 0; mt < 4; mt++) {
                const int rowa = warp_m * 64 + mt * 16 + rinA;
                const uint32_t off = swz(rowa, (ks << 1) + kbA);
                uint32_t a0, a1, a2, a3, l0, l1, l2, l3;
                ldm_x4(a0, a1, a2, a3, st + STG_A_H + off);
                ldm_x4(l0, l1, l2, l3, st + STG_A_L + off);
#pragma unroll
                for (int nt = 0; nt < 4; nt++) {
                    mma_bf16(acc[mt][nt], a0, a1, a2, a3, bh[nt][0], bh[nt][1]);
                    mma_bf16(acc[mt][nt], a0, a1, a2, a3, bl[nt][0], bl[nt][1]);
                    mma_bf16(acc[mt][nt], l0, l1, l2, l3, bh[nt][0], bh[nt][1]);
                }
            }
        }
        __syncthreads();
    }

    const int g4 = lane >> 2, t4 = lane & 3;
#pragma unroll
    for (int mt = 0; mt < 4; mt++) {
#pragma unroll
        for (int half = 0; half < 2; half++) {
            const int row = brow + warp_m * 64 + mt * 16 + g4 + half * 8;
            float* arow = attn + ((size_t)h * SQ + row) * SQ;
#pragma unroll
            for (int nt = 0; nt < 4; nt++) {
                const int col = bcol + warp_n * 32 + nt * 8 + t4 * 2;
                if (col <= row)     arow[col]     = acc[mt][nt][half * 2 + 0] * 0.125f;
                if (col + 1 <= row) arow[col + 1] = acc[mt][nt][half * 2 + 1] * 0.125f;
            }
        }
    }
}

// ================= softmax (warp-shuffle, vectorized fills) ==================
__global__ __launch_bounds__(256) void softmax_kernel(
    float* __restrict__ attn,
    __nv_bfloat16* __restrict__ ah, __nv_bfloat16* __restrict__ al)
{
    __shared__ float p[SQ];
    __shared__ float red[8];
    __shared__ float bc[2];
    const int i   = blockIdx.x;
    const int h   = blockIdx.y;
    const int tid = threadIdx.x;
    const int lane = tid & 31, warp = tid >> 5;
    const size_t rb = ((size_t)h * SQ + i) * SQ;
    float* row = attn + rb;

    float m = -INFINITY;
    for (int j = tid; j <= i; j += 256) { float s = row[j]; p[j] = s; m = fmaxf(m, s); }
    m = wred_max(m);
    if (lane == 0) red[warp] = m;
    __syncthreads();
    if (warp == 0) {
        float t = red[lane & 7];
        t = fmaxf(t, __shfl_xor_sync(0xffffffffu, t, 1));
        t = fmaxf(t, __shfl_xor_sync(0xffffffffu, t, 2));
        t = fmaxf(t, __shfl_xor_sync(0xffffffffu, t, 4));
        if (lane == 0) bc[0] = t;
    }
    __syncthreads();
    const float mx = bc[0];

    float sum = 0.0f;
    for (int j = tid; j <= i; j += 256) { float e = __expf(p[j] - mx); p[j] = e; sum += e; }
    sum = wred_sum(sum);
    __syncthreads();
    if (lane == 0) red[warp] = sum;
    __syncthreads();
    if (warp == 0) {
        float t = red[lane & 7];
        t += __shfl_xor_sync(0xffffffffu, t, 1);
        t += __shfl_xor_sync(0xffffffffu, t, 2);
        t += __shfl_xor_sync(0xffffffffu, t, 4);
        if (lane == 0) bc[1] = t;
    }
    __syncthreads();
    const float inv = 1.0f / bc[1];

    const int lim = ((i >> 7) + 1) << 7;
    for (int j = tid; j <= i; j += 256) {
        float w = p[j] * inv;
        row[j] = w;
        __nv_bfloat16 hh = __float2bfloat16_rn(w);
        ah[rb + j] = hh;
        al[rb + j] = __float2bfloat16_rn(w - __bfloat162float(hh));
    }

    // vectorized zero fills above the diagonal
    const int zs = i + 1;
    const int za = (zs + 3) & ~3;
    if (tid < za - zs && zs + tid < SQ) row[zs + tid] = 0.0f;
    const float4 zf4 = {0.0f, 0.0f, 0.0f, 0.0f};
    for (int j = za + tid * 4; j < SQ; j += 1024) *(float4*)(row + j) = zf4;
    const __nv_bfloat16 z = __float2bfloat16_rn(0.0f);
    if (tid < za - zs && zs + tid < lim) { ah[rb + zs + tid] = z; al[rb + zs + tid] = z; }
    const uint2 zu2 = {0u, 0u};
    for (int j = za + tid * 4; j < lim; j += 1024) {
        *(uint2*)(ah + rb + j) = zu2;
        *(uint2*)(al + rb + j) = zu2;
    }
}

// ================= AV mma (2-stage, occ 2): ctx = P @ V ======================
#define AV_A_H 0
#define AV_A_L 8192
#define AV_B_H 16384
#define AV_B_L 20480
#define AV_STG 24576
#define AV_SMEM (2 * AV_STG)

__global__ __launch_bounds__(256, 2) void av_mma(
    const __nv_bfloat16* __restrict__ ah, const __nv_bfloat16* __restrict__ al,
    const __nv_bfloat16* __restrict__ vh, const __nv_bfloat16* __restrict__ vl,
    __nv_bfloat16* __restrict__ ch, __nv_bfloat16* __restrict__ cl)
{
    const int brow = blockIdx.x * 128;
    const int h    = blockIdx.y;
    const __nv_bfloat16* Ah = ah + (size_t)h * SQ * SQ;
    const __nv_bfloat16* Al = al + (size_t)h * SQ * SQ;
    const __nv_bfloat16* Vh = vh + 2 * D + h * DK;
    const __nv_bfloat16* Vl = vl + 2 * D + h * DK;

    extern __shared__ char smem[];
    const uint32_t sb = smem_u32(smem);
    const int tid = threadIdx.x, wid = tid >> 5, lane = tid & 31;
    const int warp_m = wid & 3;
    const int warp_n = wid >> 2;

    float acc[2][4][4];
#pragma unroll
    for (int a = 0; a < 2; a++)
#pragma unroll
        for (int b = 0; b < 4; b++)
#pragma unroll
            for (int c = 0; c < 4; c++) acc[a][b][c] = 0.0f;

    auto load_b = [&](const __nv_bfloat16* V, int k0, uint32_t sbase) {
        int r = tid >> 3, g = tid & 7;
        cpa16(sbase + (uint32_t)(r * 128 + ((g ^ (r & 7)) << 4)),
              V + (size_t)(k0 + r) * (3 * D) + g * 8);
    };
    auto load_stage = [&](int ci, uint32_t st) {
        const int k0 = ci << 5;
        load_tileT<128>(Ah, SQ, brow, k0, st + AV_A_H, tid);
        load_tileT<128>(Al, SQ, brow, k0, st + AV_A_L, tid);
        load_b(Vh, k0, st + AV_B_H);
        load_b(Vl, k0, st + AV_B_L);
        CPA_COMMIT();
    };

    const int nch = (brow >> 5) + 4;
    load_stage(0, sb);

    const int tileA = lane >> 3;
    const int rinA  = (lane & 7) + ((tileA & 1) << 3);
    const int kbA   = tileA >> 1;
    const int i16   = lane & 15;

    for (int i = 0; i < nch; i++) {
        if (i + 1 < nch) {
            load_stage(i + 1, sb + ((i + 1) & 1) * AV_STG);
            asm volatile("cp.async.wait_group 1;" ::: "memory");
        } else {
            asm volatile("cp.async.wait_group 0;" ::: "memory");
        }
        __syncthreads();

        const uint32_t st = sb + (i & 1) * AV_STG;
#pragma unroll
        for (int ks = 0; ks < 2; ks++) {
            uint32_t bh[4][2], bl[4][2];
#pragma unroll
            for (int nt = 0; nt < 4; nt++) {
                const int krow = ks * 16 + i16;
                const int gB = warp_n * 4 + nt;
                const uint32_t off = (uint32_t)(krow * 128 + ((gB ^ (krow & 7)) << 4));
                ldm_x2t(bh[nt][0], bh[nt][1], st + AV_B_H + off);
                ldm_x2t(bl[nt][0], bl[nt][1], st + AV_B_L + off);
            }
#pragma unroll
            for (int mt = 0; mt < 2; mt++) {
                const int rowa = warp_m * 32 + mt * 16 + rinA;
                const uint32_t off = swz(rowa, (ks << 1) + kbA);
                uint32_t a0, a1, a2, a3, l0, l1, l2, l3;
                ldm_x4(a0, a1, a2, a3, st + AV_A_H + off);
                ldm_x4(l0, l1, l2, l3, st + AV_A_L + off);
#pragma unroll
                for (int nt = 0; nt < 4; nt++) {
                    mma_bf16(acc[mt][nt], a0, a1, a2, a3, bh[nt][0], bh[nt][1]);
                    mma_bf16(acc[mt][nt], a0, a1, a2, a3, bl[nt][0], bl[nt][1]);
                    mma_bf16(acc[mt][nt], l0, l1, l2, l3, bh[nt][0], bh[nt][1]);
                }
            }
        }
        __syncthreads();
    }

    const int g4 = lane >> 2, t4 = lane & 3;
#pragma unroll
    for (int mt = 0; mt < 2; mt++) {
#pragma unroll
        for (int half = 0; half < 2; half++) {
            const int row = brow + warp_m * 32 + mt * 16 + g4 + half * 8;
#pragma unroll
            for (int nt = 0; nt < 4; nt++) {
                const int col = h * DK + warp_n * 32 + nt * 8 + t4 * 2;
                float v0 = acc[mt][nt][half * 2 + 0];
                float v1 = acc[mt][nt][half * 2 + 1];
                const size_t o = (size_t)row * D + col;
                __nv_bfloat16 h0 = __float2bfloat16_rn(v0);
                __nv_bfloat16 h1 = __float2bfloat16_rn(v1);
                __nv_bfloat16 q0 = __float2bfloat16_rn(v0 - __bfloat162float(h0));
                __nv_bfloat16 q1 = __float2bfloat16_rn(v1 - __bfloat162float(h1));
                __nv_bfloat162 hp = {h0, h1}, lp = {q0, q1};
                *(__nv_bfloat162*)(ch + o) = hp;
                *(__nv_bfloat162*)(cl + o) = lp;
            }
        }
    }
}

// ================= host driver =================
struct Scratch {
    __nv_bfloat16 *nxh, *nxl, *hh, *hl, *qkvh, *qkvl, *ctxh, *ctxl, *n2h, *n2l, *ff1h, *ff1l;
    __nv_bfloat16 *attnh, *attnl;
    __nv_bfloat16 *winth, *wintl, *wqkvth, *wqkvtl, *w2th, *w2tl, *wf1th, *wf1tl, *wf2th, *wf2tl;
    __nv_bfloat16 *wonth, *wontl, *combh, *combl;
    float *p1, *n2, *attn, *bqkv, *bcomb, *zero;
};

static Scratch get_scratch() {
    static Scratch s = [] {
        Scratch t;
        void* p;
        cudaGetSymbolAddress(&p, g_nx_h);   t.nxh = (__nv_bfloat16*)p;
        cudaGetSymbolAddress(&p, g_nx_l);   t.nxl = (__nv_bfloat16*)p;
        cudaGetSymbolAddress(&p, g_h_h);    t.hh  = (__nv_bfloat16*)p;
        cudaGetSymbolAddress(&p, g_h_l);    t.hl  = (__nv_bfloat16*)p;
        cudaGetSymbolAddress(&p, g_qkv_h);  t.qkvh = (__nv_bfloat16*)p;
        cudaGetSymbolAddress(&p, g_qkv_l);  t.qkvl = (__nv_bfloat16*)p;
        cudaGetSymbolAddress(&p, g_ctx_h);  t.ctxh = (__nv_bfloat16*)p;
        cudaGetSymbolAddress(&p, g_ctx_l);  t.ctxl = (__nv_bfloat16*)p;
        cudaGetSymbolAddress(&p, g_n2_h);   t.n2h = (__nv_bfloat16*)p;
        cudaGetSymbolAddress(&p, g_n2_l);   t.n2l = (__nv_bfloat16*)p;
        cudaGetSymbolAddress(&p, g_ff1_h);  t.ff1h = (__nv_bfloat16*)p;
        cudaGetSymbolAddress(&p, g_ff1_l);  t.ff1l = (__nv_bfloat16*)p;
        cudaGetSymbolAddress(&p, g_attn_h); t.attnh = (__nv_bfloat16*)p;
        cudaGetSymbolAddress(&p, g_attn_l); t.attnl = (__nv_bfloat16*)p;
        cudaGetSymbolAddress(&p, g_wint_h); t.winth = (__nv_bfloat16*)p;
        cudaGetSymbolAddress(&p, g_wint_l); t.wintl = (__nv_bfloat16*)p;
        cudaGetSymbolAddress(&p, g_wqkvt_h); t.wqkvth = (__nv_bfloat16*)p;
        cudaGetSymbolAddress(&p, g_wqkvt_l); t.wqkvtl = (__nv_bfloat16*)p;
        cudaGetSymbolAddress(&p, g_w2t_h);  t.w2th = (__nv_bfloat16*)p;
        cudaGetSymbolAddress(&p, g_w2t_l);  t.w2tl = (__nv_bfloat16*)p;
        cudaGetSymbolAddress(&p, g_wf1t_h); t.wf1th = (__nv_bfloat16*)p;
        cudaGetSymbolAddress(&p, g_wf1t_l); t.wf1tl = (__nv_bfloat16*)p;
        cudaGetSymbolAddress(&p, g_wf2t_h); t.wf2th = (__nv_bfloat16*)p;
        cudaGetSymbolAddress(&p, g_wf2t_l); t.wf2tl = (__nv_bfloat16*)p;
        cudaGetSymbolAddress(&p, g_wo_nt_h); t.wonth = (__nv_bfloat16*)p;
        cudaGetSymbolAddress(&p, g_wo_nt_l); t.wontl = (__nv_bfloat16*)p;
        cudaGetSymbolAddress(&p, g_comb_h); t.combh = (__nv_bfloat16*)p;
        cudaGetSymbolAddress(&p, g_comb_l); t.combl = (__nv_bfloat16*)p;
        cudaGetSymbolAddress(&p, g_p1);     t.p1  = (float*)p;
        cudaGetSymbolAddress(&p, g_n2);     t.n2  = (float*)p;
        cudaGetSymbolAddress(&p, g_attn_scratch); t.attn = (float*)p;
        cudaGetSymbolAddress(&p, g_bqkv);   t.bqkv = (float*)p;
        cudaGetSymbolAddress(&p, g_bcomb);  t.bcomb = (float*)p;
        cudaGetSymbolAddress(&p, g_zero);   t.zero = (float*)p;
        cudaFuncSetAttribute((const void*)mma_gemm<64,0,1,0,0>,  cudaFuncAttributeMaxDynamicSharedMemorySize, GSMEM_64);
        cudaFuncSetAttribute((const void*)mma_gemm<64,1,0,0,1>,  cudaFuncAttributeMaxDynamicSharedMemorySize, GSMEM_64);
        cudaFuncSetAttribute((const void*)mma_gemm<128,0,1,0,0>, cudaFuncAttributeMaxDynamicSharedMemorySize, GSMEM_128);
        cudaFuncSetAttribute((const void*)mma_gemm<128,0,1,1,0>, cudaFuncAttributeMaxDynamicSharedMemorySize, GSMEM_128);
        cudaFuncSetAttribute((const void*)score_mma, cudaFuncAttributeMaxDynamicSharedMemorySize, SCORE_SMEM);
        cudaFuncSetAttribute((const void*)av_mma,    cudaFuncAttributeMaxDynamicSharedMemorySize, AV_SMEM);
        return t;
    }();
    return s;
}

extern "C" void kernel_launch(void* const* d_in, const int* in_sizes, int n_in,
                              void* d_out, int out_size)
{
    const float* x     = (const float*)d_in[0];
    const float* g1    = (const float*)d_in[1];
    const float* beta1 = (const float*)d_in[2];
    const float* W_in  = (const float*)d_in[3];
    const float* b_in  = (const float*)d_in[4];
    const float* Wq    = (const float*)d_in[5];
    const float* bq    = (const float*)d_in[6];
    const float* Wk    = (const float*)d_in[7];
    const float* bk    = (const float*)d_in[8];
    const float* Wv    = (const float*)d_in[9];
    const float* bv    = (const float*)d_in[10];
    const float* Wo    = (const float*)d_in[11];
    const float* bo    = (const float*)d_in[12];
    const float* W2    = (const float*)d_in[13];
    const float* b2    = (const float*)d_in[14];
    const float* g2    = (const float*)d_in[15];
    const float* beta2 = (const float*)d_in[16];
    const float* Wf1   = (const float*)d_in[17];
    const float* bf1   = (const float*)d_in[18];
    const float* Wf2   = (const float*)d_in[19];
    const float* bf2   = (const float*)d_in[20];

    Scratch s = get_scratch();

    float* out  = (float*)d_out;
    const long long full = (long long)SQ * D + (long long)NH * SQ * SQ;
    float* attn = ((long long)out_size >= full) ? (out + (size_t)SQ * D) : s.attn;

    dim3 blk(256);
    dim3 wblk(32, 8);

    // #1: weight prep (z: W_in, Wq, Wk, Wv, W2, Wo-straight) + qkv bias concat
    wprep_dd<<<dim3(32, 32, 6), wblk>>>(
        W_in, Wq, Wk, Wv, Wo, W2, bq, bk, bv,
        s.winth, s.wintl, s.wqkvth, s.wqkvtl, s.wonth, s.wontl, s.w2th, s.w2tl, s.bqkv);
    // #2: ff weight prep
    wprep_ff<<<dim3(128, 32, 2), wblk>>>(Wf1, Wf2, s.wf1th, s.wf1tl, s.wf2th, s.wf2tl);
    // #3: b_comb = bo@W2 + b2
    bias_fold<<<4, 256>>>(bo, W2, b2, s.bcomb);
    // #4: comb[b,a] = sum_mid W2T[b,mid]*Wo[a,mid]  (= (Wo@W2) in B-operand layout)
    mma_gemm<64,0,1,0,0><<<dim3(D/64, D/128), 256, GSMEM_64>>>(
        s.w2th, s.w2tl, s.wonth, s.wontl, s.zero, nullptr, nullptr, s.combh, s.combl, D, D);
    // #5: LN1 -> split
    ln_kernel<0,1><<<SQ, blk>>>(x, g1, beta1, nullptr, s.nxh, s.nxl);
    // #6: h = nx @ W_in + b_in   [ncu -s 5 captures this; comparator vs R9/R11]
    mma_gemm<64,0,1,0,0><<<dim3(D/64, SQ/128), 256, GSMEM_64>>>(
        s.nxh, s.nxl, s.winth, s.wintl, b_in, nullptr, nullptr, s.hh, s.hl, D, D);
    // #7: qkv (packed N=3072)
    mma_gemm<128,0,1,0,0><<<dim3(3*D/128, SQ/128), 256, GSMEM_128>>>(
        s.hh, s.hl, s.wqkvth, s.wqkvtl, s.bqkv, nullptr, nullptr, s.qkvh, s.qkvl, 3*D, D);
    // #8: scores
    score_mma<<<dim3(SQ/128, SQ/128, NH), 256, SCORE_SMEM>>>(
        s.qkvh, s.qkvl, s.qkvh + D, s.qkvl + D, attn);
    // #9: softmax
    softmax_kernel<<<dim3(SQ, NH), blk>>>(attn, s.attnh, s.attnl);
    // #10: AV
    av_mma<<<dim3(SQ/128, NH), 256, AV_SMEM>>>(
        s.attnh, s.attnl, s.qkvh, s.qkvl, s.ctxh, s.ctxl);
    // #11: p1 = x + ctx @ (Wo@W2) + b_comb  (fused Wo/W2, one GEMM instead of two)
    mma_gemm<64,1,0,0,1><<<dim3(D/64, SQ/128), 256, GSMEM_64>>>(
        s.ctxh, s.ctxl, s.combh, s.combl, s.bcomb, x, s.p1, nullptr, nullptr, D, D);
    // #12: LN2
    ln_kernel<1,1><<<SQ, blk>>>(s.p1, g2, beta2, s.n2, s.n2h, s.n2l);
    // #13: ff1 = relu(n2 @ Wf1 + bf1)
    mma_gemm<128,0,1,1,0><<<dim3(DFF/128, SQ/128), 256, GSMEM_128>>>(
        s.n2h, s.n2l, s.wf1th, s.wf1tl, bf1, nullptr, nullptr, s.ff1h, s.ff1l, DFF, D);
    // #14: out = n2 + ff1 @ Wf2 + bf2
    mma_gemm<64,1,0,0,1><<<dim3(D/64, SQ/128), 256, GSMEM_64>>>(
        s.ff1h, s.ff1l, s.wf2th, s.wf2tl, bf2, s.n2, out, nullptr, nullptr, D, DFF);
}

// round 13
// speedup vs baseline: 1.3371x; 1.3371x over previous
#include <cuda_runtime.h>
#include <cuda_bf16.h>
#include <math.h>
#include <stdint.h>

#define SQ   2048
#define D    1024
#define NH   16
#define DK   64
#define DFF  4096

// ================= PTX helpers (baseline ISA, sm_80-level) ===================
__device__ __forceinline__ uint32_t smem_u32(const void* p) {
    uint32_t a;
    asm("{ .reg .u64 t; cvta.to.shared.u64 t, %1; cvt.u32.u64 %0, t; }" : "=r"(a) : "l"(p));
    return a;
}
__device__ __forceinline__ void cpa16(uint32_t dst, const void* src) {
    asm volatile("cp.async.cg.shared.global [%0], [%1], 16;" :: "r"(dst), "l"(src));
}
#define CPA_COMMIT() asm volatile("cp.async.commit_group;" ::: "memory")
__device__ __forceinline__ void ldm_x4(uint32_t& r0, uint32_t& r1, uint32_t& r2, uint32_t& r3, uint32_t addr) {
    asm volatile("ldmatrix.sync.aligned.m8n8.x4.shared.b16 {%0,%1,%2,%3}, [%4];"
                 : "=r"(r0), "=r"(r1), "=r"(r2), "=r"(r3) : "r"(addr));
}
__device__ __forceinline__ void ldm_x2(uint32_t& r0, uint32_t& r1, uint32_t addr) {
    asm volatile("ldmatrix.sync.aligned.m8n8.x2.shared.b16 {%0,%1}, [%2];"
                 : "=r"(r0), "=r"(r1) : "r"(addr));
}
__device__ __forceinline__ uint32_t f2tf(uint32_t x) {
    uint32_t r;
    asm("cvt.rna.tf32.f32 %0, %1;" : "=r"(r) : "f"(__uint_as_float(x)));
    return r;
}
__device__ __forceinline__ void mma_tf32(float* c, uint32_t a0, uint32_t a1, uint32_t a2, uint32_t a3,
                                         uint32_t b0, uint32_t b1) {
    asm volatile("mma.sync.aligned.m16n8k8.row.col.f32.tf32.tf32.f32 "
                 "{%0,%1,%2,%3}, {%4,%5,%6,%7}, {%8,%9}, {%0,%1,%2,%3};"
                 : "+f"(c[0]), "+f"(c[1]), "+f"(c[2]), "+f"(c[3])
                 : "r"(a0), "r"(a1), "r"(a2), "r"(a3), "r"(b0), "r"(b1));
}
__device__ __forceinline__ float wred_max(float v) {
#pragma unroll
    for (int o = 16; o > 0; o >>= 1) v = fmaxf(v, __shfl_xor_sync(0xffffffffu, v, o));
    return v;
}
__device__ __forceinline__ float wred_sum(float v) {
#pragma unroll
    for (int o = 16; o > 0; o >>= 1) v += __shfl_xor_sync(0xffffffffu, v, o);
    return v;
}

// ================= scratch (all fp32 now) ====================================
__device__ float g_nx[SQ * D];
__device__ float g_h[SQ * D];
__device__ float g_qkv[SQ * 3 * D];
__device__ float g_ctx[SQ * D];
__device__ float g_mha[SQ * D];
__device__ float g_p1[SQ * D];
__device__ float g_n2[SQ * D];
__device__ float g_ff1[SQ * DFF];
__device__ float g_attn_scratch[(size_t)NH * SQ * SQ];
// transposed weights [N, K] fp32
__device__ float g_wint[D * D];
__device__ float g_wqkvt[3 * D * D];
__device__ float g_wot[D * D];
__device__ float g_w2t[D * D];
__device__ float g_wf1t[DFF * D];
__device__ float g_wf2t[D * DFF];
__device__ float g_bqkv[3 * D];

// ================= weight prep: transpose fp32 ===============================
__device__ __forceinline__ void wprep_tile(
    const float* __restrict__ W, float* __restrict__ T,
    int K, int N, int rowoff, int n0, int k0)
{
    __shared__ float t[32][33];
    const int tx = threadIdx.x, ty = threadIdx.y;
    for (int i = ty; i < 32; i += 8)
        t[i][tx] = W[(size_t)(k0 + i) * N + n0 + tx];
    __syncthreads();
    for (int i = ty; i < 32; i += 8)
        T[(size_t)(rowoff + n0 + i) * K + k0 + tx] = t[tx][i];
}

__global__ __launch_bounds__(256) void wprep_dd(
    const float* __restrict__ W_in, const float* __restrict__ Wq,
    const float* __restrict__ Wk,   const float* __restrict__ Wv,
    const float* __restrict__ Wo,   const float* __restrict__ W2,
    const float* __restrict__ bq,   const float* __restrict__ bk,
    const float* __restrict__ bv,
    float* wint, float* wqkvt, float* wot, float* w2t, float* bqkv)
{
    const int z = blockIdx.z;
    const float* W; float* T; int rowoff = 0;
    switch (z) {
        case 0:  W = W_in; T = wint;  break;
        case 1:  W = Wq;   T = wqkvt; rowoff = 0;     break;
        case 2:  W = Wk;   T = wqkvt; rowoff = D;     break;
        case 3:  W = Wv;   T = wqkvt; rowoff = 2 * D; break;
        case 4:  W = Wo;   T = wot;   break;
        default: W = W2;   T = w2t;   break;
    }
    wprep_tile(W, T, D, D, rowoff, blockIdx.x * 32, blockIdx.y * 32);
    if (z >= 1 && z <= 3 && blockIdx.x == 0 && blockIdx.y == 0) {
        const float* b = (z == 1) ? bq : (z == 2) ? bk : bv;
        for (int j = threadIdx.y * 32 + threadIdx.x; j < D; j += 256)
            bqkv[(z - 1) * D + j] = b[j];
    }
}

__global__ __launch_bounds__(256) void wprep_ff(
    const float* __restrict__ Wf1, const float* __restrict__ Wf2,
    float* f1t, float* f2t)
{
    if (blockIdx.z == 0)
        wprep_tile(Wf1, f1t, D, DFF, 0, blockIdx.x * 32, blockIdx.y * 32);
    else
        wprep_tile(Wf2, f2t, DFF, D, 0, blockIdx.y * 32, blockIdx.x * 32);
}

// ================= LayerNorm (warp-shuffle) ==================================
__global__ __launch_bounds__(256) void ln_kernel(
    const float* __restrict__ x, const float* __restrict__ g,
    const float* __restrict__ b, float* __restrict__ outf)
{
    __shared__ float red[8];
    __shared__ float bc[2];
    const int row = blockIdx.x;
    const int tid = threadIdx.x;
    const int lane = tid & 31, warp = tid >> 5;
    float4 v = *(const float4*)(x + (size_t)row * D + tid * 4);

    float s = wred_sum(v.x + v.y + v.z + v.w);
    if (lane == 0) red[warp] = s;
    __syncthreads();
    if (warp == 0) {
        float t = red[lane & 7];
        t += __shfl_xor_sync(0xffffffffu, t, 1);
        t += __shfl_xor_sync(0xffffffffu, t, 2);
        t += __shfl_xor_sync(0xffffffffu, t, 4);
        if (lane == 0) bc[0] = t;
    }
    __syncthreads();
    const float mean = bc[0] * (1.0f / D);
    const float dx = v.x - mean, dy = v.y - mean, dz = v.z - mean, dw = v.w - mean;

    float s2 = wred_sum(dx * dx + dy * dy + dz * dz + dw * dw);
    if (lane == 0) red[warp] = s2;
    __syncthreads();
    if (warp == 0) {
        float t = red[lane & 7];
        t += __shfl_xor_sync(0xffffffffu, t, 1);
        t += __shfl_xor_sync(0xffffffffu, t, 2);
        t += __shfl_xor_sync(0xffffffffu, t, 4);
        if (lane == 0) bc[1] = t;
    }
    __syncthreads();
    const float inv = 1.0f / (sqrtf(bc[1] * (1.0f / D)) + 1e-6f);

    float4 gg = *(const float4*)(g + tid * 4);
    float4 bb = *(const float4*)(b + tid * 4);
    float4 o4;
    o4.x = gg.x * dx * inv + bb.x;
    o4.y = gg.y * dy * inv + bb.y;
    o4.z = gg.z * dz * inv + bb.z;
    o4.w = gg.w * dw * inv + bb.w;
    *(float4*)(outf + (size_t)row * D + tid * 4) = o4;
}

// ================= shared GEMM plumbing (fp32 tiles, 128B rows) ==============
// tile layout: [rows][32 fp32] = 128B rows, 8 granules of 16B, xor-swizzled
__device__ __forceinline__ uint32_t swzf(int row, int g) {
    return (uint32_t)(row * 128 + ((g ^ (row & 7)) << 4));
}

template<int ROWS>
__device__ __forceinline__ void load_tf(
    const float* __restrict__ gp, int ld, int row0, int k0, uint32_t sbase, int tid)
{
#pragma unroll
    for (int it = 0; it < ROWS / 32; it++) {
        int c = tid + (it << 8);
        int row = c >> 3, g = c & 7;
        cpa16(sbase + swzf(row, g), gp + (size_t)(row0 + row) * ld + k0 + g * 4);
    }
}

// ================= TF32 GEMM (2-stage, occ 2): C = A[M,K] @ T[N,K]^T =========
template<int BN, int RELU, int RESID>
__global__ __launch_bounds__(256, 2) void tf_gemm(
    const float* __restrict__ A, const float* __restrict__ B,
    const float* __restrict__ bias, const float* __restrict__ res,
    float* __restrict__ C, int N, int K)
{
    constexpr int MT  = (BN == 128) ? 4 : 2;
    constexpr int SA  = 0;
    constexpr int SB  = 16384;             // A tile = 128*128B
    constexpr int SSZ = 16384 + BN * 128;  // + B tile

    extern __shared__ char smem[];
    const uint32_t sb = smem_u32(smem);
    const int tid = threadIdx.x, wid = tid >> 5, lane = tid & 31;
    const int warp_m = (BN == 128) ? (wid & 1) : (wid & 3);
    const int warp_n = (BN == 128) ? (wid >> 1) : (wid >> 2);
    const int brow = blockIdx.y * 128, bcol = blockIdx.x * BN;

    float acc[MT][4][4];
#pragma unroll
    for (int a = 0; a < MT; a++)
#pragma unroll
        for (int b = 0; b < 4; b++)
#pragma unroll
            for (int c = 0; c < 4; c++) acc[a][b][c] = 0.0f;

    const int nch = K >> 5;
    load_tf<128>(A, K, brow, 0, sb + SA, tid);
    load_tf<BN>(B, K, bcol, 0, sb + SB, tid);
    CPA_COMMIT();

    const int tileA = lane >> 3;
    const int rinA  = (lane & 7) + ((tileA & 1) << 3);
    const int gA    = tileA >> 1;
    const int i16   = lane & 15;
    const int rinB  = i16 & 7;
    const int gB    = i16 >> 3;

    for (int i = 0; i < nch; i++) {
        if (i + 1 < nch) {
            const uint32_t st = sb + ((i + 1) & 1) * SSZ;
            const int k0 = (i + 1) << 5;
            load_tf<128>(A, K, brow, k0, st + SA, tid);
            load_tf<BN>(B, K, bcol, k0, st + SB, tid);
            CPA_COMMIT();
            asm volatile("cp.async.wait_group 1;" ::: "memory");
        } else {
            asm volatile("cp.async.wait_group 0;" ::: "memory");
        }
        __syncthreads();

        const uint32_t st = sb + (i & 1) * SSZ;
#pragma unroll
        for (int ks = 0; ks < 4; ks++) {
            uint32_t b0[4], b1[4];
#pragma unroll
            for (int nt = 0; nt < 4; nt++) {
                const int rowb = warp_n * 32 + nt * 8 + rinB;
                ldm_x2(b0[nt], b1[nt], st + SB + swzf(rowb, 2 * ks + gB));
                b0[nt] = f2tf(b0[nt]);
                b1[nt] = f2tf(b1[nt]);
            }
#pragma unroll
            for (int mt = 0; mt < MT; mt++) {
                const int rowa = warp_m * (MT * 16) + mt * 16 + rinA;
                uint32_t a0, a1, a2, a3;
                ldm_x4(a0, a1, a2, a3, st + SA + swzf(rowa, 2 * ks + gA));
                a0 = f2tf(a0); a1 = f2tf(a1); a2 = f2tf(a2); a3 = f2tf(a3);
#pragma unroll
                for (int nt = 0; nt < 4; nt++)
                    mma_tf32(acc[mt][nt], a0, a1, a2, a3, b0[nt], b1[nt]);
            }
        }
        __syncthreads();
    }

    const int g4 = lane >> 2, t4 = lane & 3;
#pragma unroll
    for (int mt = 0; mt < MT; mt++) {
#pragma unroll
        for (int half = 0; half < 2; half++) {
            const int row = brow + warp_m * (MT * 16) + mt * 16 + g4 + half * 8;
#pragma unroll
            for (int nt = 0; nt < 4; nt++) {
                const int col = bcol + warp_n * 32 + nt * 8 + t4 * 2;
                float v0 = acc[mt][nt][half * 2 + 0] + bias[col];
                float v1 = acc[mt][nt][half * 2 + 1] + bias[col + 1];
                if (RELU) { v0 = fmaxf(v0, 0.0f); v1 = fmaxf(v1, 0.0f); }
                const size_t o = (size_t)row * N + col;
                if (RESID) { v0 += res[o]; v1 += res[o + 1]; }
                float2 f2 = {v0, v1};
                *(float2*)(C + o) = f2;
            }
        }
    }
}

#define GSMEM_128 (2 * (16384 + 16384))
#define GSMEM_64  (2 * (16384 + 8192))

// ================= score (TF32): S = (Q K^T)/8, causal =======================
#define SC_SSZ (16384 + 16384)
#define SCORE_SMEM (2 * SC_SSZ)

__global__ __launch_bounds__(256, 2) void score_mma(
    const float* __restrict__ q, const float* __restrict__ k,
    float* __restrict__ attn)
{
    const int brow = blockIdx.y * 128, bcol = blockIdx.x * 128;
    if (bcol >= brow + 128) return;
    const int h = blockIdx.z;
    const float* A = q + h * DK;
    const float* B = k + h * DK;

    extern __shared__ char smem[];
    const uint32_t sb = smem_u32(smem);
    const int tid = threadIdx.x, wid = tid >> 5, lane = tid & 31;
    const int warp_m = wid & 1, warp_n = wid >> 1;

    float acc[4][4][4];
#pragma unroll
    for (int a = 0; a < 4; a++)
#pragma unroll
        for (int b = 0; b < 4; b++)
#pragma unroll
            for (int c = 0; c < 4; c++) acc[a][b][c] = 0.0f;

    load_tf<128>(A, 3 * D, brow, 0, sb, tid);
    load_tf<128>(B, 3 * D, bcol, 0, sb + 16384, tid);
    CPA_COMMIT();

    const int tileA = lane >> 3;
    const int rinA  = (lane & 7) + ((tileA & 1) << 3);
    const int gA    = tileA >> 1;
    const int i16   = lane & 15;
    const int rinB  = i16 & 7;
    const int gB    = i16 >> 3;

    for (int i = 0; i < 2; i++) {
        if (i == 0) {
            const uint32_t st = sb + SC_SSZ;
            load_tf<128>(A, 3 * D, brow, 32, st, tid);
            load_tf<128>(B, 3 * D, bcol, 32, st + 16384, tid);
            CPA_COMMIT();
            asm volatile("cp.async.wait_group 1;" ::: "memory");
        } else {
            asm volatile("cp.async.wait_group 0;" ::: "memory");
        }
        __syncthreads();

        const uint32_t st = sb + (i & 1) * SC_SSZ;
#pragma unroll
        for (int ks = 0; ks < 4; ks++) {
            uint32_t b0[4], b1[4];
#pragma unroll
            for (int nt = 0; nt < 4; nt++) {
                const int rowb = warp_n * 32 + nt * 8 + rinB;
                ldm_x2(b0[nt], b1[nt], st + 16384 + swzf(rowb, 2 * ks + gB));
                b0[nt] = f2tf(b0[nt]);
                b1[nt] = f2tf(b1[nt]);
            }
#pragma unroll
            for (int mt = 0; mt < 4; mt++) {
                const int rowa = warp_m * 64 + mt * 16 + rinA;
                uint32_t a0, a1, a2, a3;
                ldm_x4(a0, a1, a2, a3, st + swzf(rowa, 2 * ks + gA));
                a0 = f2tf(a0); a1 = f2tf(a1); a2 = f2tf(a2); a3 = f2tf(a3);
#pragma unroll
                for (int nt = 0; nt < 4; nt++)
                    mma_tf32(acc[mt][nt], a0, a1, a2, a3, b0[nt], b1[nt]);
            }
        }
        __syncthreads();
    }

    const int g4 = lane >> 2, t4 = lane & 3;
#pragma unroll
    for (int mt = 0; mt < 4; mt++) {
#pragma unroll
        for (int half = 0; half < 2; half++) {
            const int row = brow + warp_m * 64 + mt * 16 + g4 + half * 8;
            float* arow = attn + ((size_t)h * SQ + row) * SQ;
#pragma unroll
            for (int nt = 0; nt < 4; nt++) {
                const int col = bcol + warp_n * 32 + nt * 8 + t4 * 2;
                if (col <= row)     arow[col]     = acc[mt][nt][half * 2 + 0] * 0.125f;
                if (col + 1 <= row) arow[col + 1] = acc[mt][nt][half * 2 + 1] * 0.125f;
            }
        }
    }
}

// ================= softmax (fp32 only, vectorized fills) =====================
__global__ __launch_bounds__(256) void softmax_kernel(float* __restrict__ attn)
{
    __shared__ float p[SQ];
    __shared__ float red[8];
    __shared__ float bc[2];
    const int i   = blockIdx.x;
    const int h   = blockIdx.y;
    const int tid = threadIdx.x;
    const int lane = tid & 31, warp = tid >> 5;
    float* row = attn + ((size_t)h * SQ + i) * SQ;

    float m = -INFINITY;
    for (int j = tid; j <= i; j += 256) { float s = row[j]; p[j] = s; m = fmaxf(m, s); }
    m = wred_max(m);
    if (lane == 0) red[warp] = m;
    __syncthreads();
    if (warp == 0) {
        float t = red[lane & 7];
        t = fmaxf(t, __shfl_xor_sync(0xffffffffu, t, 1));
        t = fmaxf(t, __shfl_xor_sync(0xffffffffu, t, 2));
        t = fmaxf(t, __shfl_xor_sync(0xffffffffu, t, 4));
        if (lane == 0) bc[0] = t;
    }
    __syncthreads();
    const float mx = bc[0];

    float sum = 0.0f;
    for (int j = tid; j <= i; j += 256) { float e = __expf(p[j] - mx); p[j] = e; sum += e; }
    sum = wred_sum(sum);
    __syncthreads();
    if (lane == 0) red[warp] = sum;
    __syncthreads();
    if (warp == 0) {
        float t = red[lane & 7];
        t += __shfl_xor_sync(0xffffffffu, t, 1);
        t += __shfl_xor_sync(0xffffffffu, t, 2);
        t += __shfl_xor_sync(0xffffffffu, t, 4);
        if (lane == 0) bc[1] = t;
    }
    __syncthreads();
    const float inv = 1.0f / bc[1];

    for (int j = tid; j <= i; j += 256) row[j] = p[j] * inv;

    // vectorized zero fill [i+1, SQ)
    const int zs = i + 1;
    const int za = (zs + 3) & ~3;
    if (tid < za - zs && zs + tid < SQ) row[zs + tid] = 0.0f;
    const float4 zf4 = {0.0f, 0.0f, 0.0f, 0.0f};
    for (int j = za + tid * 4; j < SQ; j += 1024) *(float4*)(row + j) = zf4;
}

// ================= AV (TF32): ctx = P @ V ====================================
// A = attn fp32 [i, j] ld SQ; B = V rows [j][d] (d contiguous, ld 3D), pad-72 tile.
#define AV_A   0
#define AV_B   16384
#define AV_SSZ (16384 + 32 * 72 * 4)     // 16384 + 9216 = 25600
#define AV_SMEM (2 * AV_SSZ)

__global__ __launch_bounds__(256, 2) void av_mma(
    const float* __restrict__ attn, const float* __restrict__ v,
    float* __restrict__ ctx)
{
    const int brow = blockIdx.x * 128;
    const int h    = blockIdx.y;
    const float* A = attn + (size_t)h * SQ * SQ;
    const float* V = v + 2 * D + h * DK;

    extern __shared__ char smem[];
    const uint32_t sb = smem_u32(smem);
    float* fsm = (float*)smem;
    const int tid = threadIdx.x, wid = tid >> 5, lane = tid & 31;
    const int warp_m = wid & 3;     // 4 x 32 rows
    const int warp_n = wid >> 2;    // 2 x 32 cols

    float acc[2][4][4];
#pragma unroll
    for (int a = 0; a < 2; a++)
#pragma unroll
        for (int b = 0; b < 4; b++)
#pragma unroll
            for (int c = 0; c < 4; c++) acc[a][b][c] = 0.0f;

    auto load_stage = [&](int ci, uint32_t st) {
        const int k0 = ci << 5;
        load_tf<128>(A, SQ, brow, k0, st + AV_A, tid);
        // V tile: 32 rows x 64 fp32, stride 72 floats (288B)
#pragma unroll
        for (int it = 0; it < 2; it++) {
            int c = tid + (it << 8);
            int r = c >> 4, g = c & 15;
            cpa16(st + AV_B + (uint32_t)(r * 288 + g * 16),
                  V + (size_t)(k0 + r) * (3 * D) + g * 4);
        }
        CPA_COMMIT();
    };

    const int nch = (brow >> 5) + 4;
    load_stage(0, sb);

    const int tileA = lane >> 3;
    const int rinA  = (lane & 7) + ((tileA & 1) << 3);
    const int gA    = tileA >> 1;
    const int g4 = lane >> 2, t4 = lane & 3;

    for (int i = 0; i < nch; i++) {
        if (i + 1 < nch) {
            load_stage(i + 1, sb + ((i + 1) & 1) * AV_SSZ);
            asm volatile("cp.async.wait_group 1;" ::: "memory");
        } else {
            asm volatile("cp.async.wait_group 0;" ::: "memory");
        }
        __syncthreads();

        const uint32_t st = sb + (i & 1) * AV_SSZ;
        const float* vs = fsm + ((i & 1) * AV_SSZ + AV_B) / 4;
#pragma unroll
        for (int ks = 0; ks < 4; ks++) {
            uint32_t b0[4], b1[4];
#pragma unroll
            for (int nt = 0; nt < 4; nt++) {
                const int nn = warp_n * 32 + nt * 8 + g4;
                const int kk = ks * 8 + t4;
                b0[nt] = f2tf(__float_as_uint(vs[kk * 72 + nn]));
                b1[nt] = f2tf(__float_as_uint(vs[(kk + 4) * 72 + nn]));
            }
#pragma unroll
            for (int mt = 0; mt < 2; mt++) {
                const int rowa = warp_m * 32 + mt * 16 + rinA;
                uint32_t a0, a1, a2, a3;
                ldm_x4(a0, a1, a2, a3, st + AV_A + swzf(rowa, 2 * ks + gA));
                a0 = f2tf(a0); a1 = f2tf(a1); a2 = f2tf(a2); a3 = f2tf(a3);
#pragma unroll
                for (int nt = 0; nt < 4; nt++)
                    mma_tf32(acc[mt][nt], a0, a1, a2, a3, b0[nt], b1[nt]);
            }
        }
        __syncthreads();
    }

#pragma unroll
    for (int mt = 0; mt < 2; mt++) {
#pragma unroll
        for (int half = 0; half < 2; half++) {
            const int row = brow + warp_m * 32 + mt * 16 + g4 + half * 8;
#pragma unroll
            for (int nt = 0; nt < 4; nt++) {
                const int col = h * DK + warp_n * 32 + nt * 8 + t4 * 2;
                float2 f2 = {acc[mt][nt][half * 2 + 0], acc[mt][nt][half * 2 + 1]};
                *(float2*)(ctx + (size_t)row * D + col) = f2;
            }
        }
    }
}

// ================= host driver =================
struct Scratch {
    float *nx, *h, *qkv, *ctx, *mha, *p1, *n2, *ff1, *attn;
    float *wint, *wqkvt, *wot, *w2t, *wf1t, *wf2t, *bqkv;
};

static Scratch get_scratch() {
    static Scratch s = [] {
        Scratch t;
        void* p;
        cudaGetSymbolAddress(&p, g_nx);    t.nx   = (float*)p;
        cudaGetSymbolAddress(&p, g_h);     t.h    = (float*)p;
        cudaGetSymbolAddress(&p, g_qkv);   t.qkv  = (float*)p;
        cudaGetSymbolAddress(&p, g_ctx);   t.ctx  = (float*)p;
        cudaGetSymbolAddress(&p, g_mha);   t.mha  = (float*)p;
        cudaGetSymbolAddress(&p, g_p1);    t.p1   = (float*)p;
        cudaGetSymbolAddress(&p, g_n2);    t.n2   = (float*)p;
        cudaGetSymbolAddress(&p, g_ff1);   t.ff1  = (float*)p;
        cudaGetSymbolAddress(&p, g_attn_scratch); t.attn = (float*)p;
        cudaGetSymbolAddress(&p, g_wint);  t.wint  = (float*)p;
        cudaGetSymbolAddress(&p, g_wqkvt); t.wqkvt = (float*)p;
        cudaGetSymbolAddress(&p, g_wot);   t.wot   = (float*)p;
        cudaGetSymbolAddress(&p, g_w2t);   t.w2t   = (float*)p;
        cudaGetSymbolAddress(&p, g_wf1t);  t.wf1t  = (float*)p;
        cudaGetSymbolAddress(&p, g_wf2t);  t.wf2t  = (float*)p;
        cudaGetSymbolAddress(&p, g_bqkv);  t.bqkv  = (float*)p;
        cudaFuncSetAttribute((const void*)tf_gemm<64,0,0>,  cudaFuncAttributeMaxDynamicSharedMemorySize, GSMEM_64);
        cudaFuncSetAttribute((const void*)tf_gemm<64,0,1>,  cudaFuncAttributeMaxDynamicSharedMemorySize, GSMEM_64);
        cudaFuncSetAttribute((const void*)tf_gemm<128,0,0>, cudaFuncAttributeMaxDynamicSharedMemorySize, GSMEM_128);
        cudaFuncSetAttribute((const void*)tf_gemm<128,1,0>, cudaFuncAttributeMaxDynamicSharedMemorySize, GSMEM_128);
        cudaFuncSetAttribute((const void*)score_mma, cudaFuncAttributeMaxDynamicSharedMemorySize, SCORE_SMEM);
        cudaFuncSetAttribute((const void*)av_mma,    cudaFuncAttributeMaxDynamicSharedMemorySize, AV_SMEM);
        return t;
    }();
    return s;
}

extern "C" void kernel_launch(void* const* d_in, const int* in_sizes, int n_in,
                              void* d_out, int out_size)
{
    const float* x     = (const float*)d_in[0];
    const float* g1    = (const float*)d_in[1];
    const float* beta1 = (const float*)d_in[2];
    const float* W_in  = (const float*)d_in[3];
    const float* b_in  = (const float*)d_in[4];
    const float* Wq    = (const float*)d_in[5];
    const float* bq    = (const float*)d_in[6];
    const float* Wk    = (const float*)d_in[7];
    const float* bk    = (const float*)d_in[8];
    const float* Wv    = (const float*)d_in[9];
    const float* bv    = (const float*)d_in[10];
    const float* Wo    = (const float*)d_in[11];
    const float* bo    = (const float*)d_in[12];
    const float* W2    = (const float*)d_in[13];
    const float* b2    = (const float*)d_in[14];
    const float* g2    = (const float*)d_in[15];
    const float* beta2 = (const float*)d_in[16];
    const float* Wf1   = (const float*)d_in[17];
    const float* bf1   = (const float*)d_in[18];
    const float* Wf2   = (const float*)d_in[19];
    const float* bf2   = (const float*)d_in[20];

    Scratch s = get_scratch();

    float* out  = (float*)d_out;
    const long long full = (long long)SQ * D + (long long)NH * SQ * SQ;
    float* attn = ((long long)out_size >= full) ? (out + (size_t)SQ * D) : s.attn;

    dim3 blk(256);
    dim3 wblk(32, 8);

    // #1/#2: weight prep (fp32 transpose only)
    wprep_dd<<<dim3(32, 32, 6), wblk>>>(
        W_in, Wq, Wk, Wv, Wo, W2, bq, bk, bv,
        s.wint, s.wqkvt, s.wot, s.w2t, s.bqkv);
    wprep_ff<<<dim3(128, 32, 2), wblk>>>(Wf1, Wf2, s.wf1t, s.wf2t);

    // #3: LN1
    ln_kernel<<<SQ, blk>>>(x, g1, beta1, s.nx);
    // #4: h = nx @ W_in + b_in (BN=64, grid 256)
    tf_gemm<64,0,0><<<dim3(D/64, SQ/128), 256, GSMEM_64>>>(
        s.nx, s.wint, b_in, nullptr, s.h, D, D);
    // #5: qkv packed (BN=128, grid 384)
    tf_gemm<128,0,0><<<dim3(3*D/128, SQ/128), 256, GSMEM_128>>>(
        s.h, s.wqkvt, s.bqkv, nullptr, s.qkv, 3*D, D);
    // #6: scores   [ncu -s 5 captures this]
    score_mma<<<dim3(SQ/128, SQ/128, NH), 256, SCORE_SMEM>>>(
        s.qkv, s.qkv + D, attn);
    // #7: softmax (fp32 only)
    softmax_kernel<<<dim3(SQ, NH), blk>>>(attn);
    // #8: AV
    av_mma<<<dim3(SQ/128, NH), 256, AV_SMEM>>>(attn, s.qkv, s.ctx);
    // #9: mha = ctx @ Wo + bo
    tf_gemm<64,0,0><<<dim3(D/64, SQ/128), 256, GSMEM_64>>>(
        s.ctx, s.wot, bo, nullptr, s.mha, D, D);
    // #10: p1 = x + mha @ W2 + b2
    tf_gemm<64,0,1><<<dim3(D/64, SQ/128), 256, GSMEM_64>>>(
        s.mha, s.w2t, b2, x, s.p1, D, D);
    // #11: LN2
    ln_kernel<<<SQ, blk>>>(s.p1, g2, beta2, s.n2);
    // #12: ff1 = relu(n2 @ Wf1 + bf1) (BN=128, grid 512)
    tf_gemm<128,1,0><<<dim3(DFF/128, SQ/128), 256, GSMEM_128>>>(
        s.n2, s.wf1t, bf1, nullptr, s.ff1, DFF, D);
    // #13: out = n2 + ff1 @ Wf2 + bf2 (K=4096)
    tf_gemm<64,0,1><<<dim3(D/64, SQ/128), 256, GSMEM_64>>>(
        s.ff1, s.wf2t, bf2, s.n2, out, D, DFF);
}

// round 15
// speedup vs baseline: 1.4401x; 1.0770x over previous
#include <cuda_runtime.h>
#include <cuda_bf16.h>
#include <math.h>
#include <stdint.h>

#define SQ   2048
#define D    1024
#define NH   16
#define DK   64
#define DFF  4096

// ================= PTX helpers (baseline ISA, sm_80-level) ===================
__device__ __forceinline__ uint32_t smem_u32(const void* p) {
    uint32_t a;
    asm("{ .reg .u64 t; cvta.to.shared.u64 t, %1; cvt.u32.u64 %0, t; }" : "=r"(a) : "l"(p));
    return a;
}
__device__ __forceinline__ void cpa16(uint32_t dst, const void* src) {
    asm volatile("cp.async.cg.shared.global [%0], [%1], 16;" :: "r"(dst), "l"(src));
}
#define CPA_COMMIT() asm volatile("cp.async.commit_group;" ::: "memory")
__device__ __forceinline__ void ldm_x4(uint32_t& r0, uint32_t& r1, uint32_t& r2, uint32_t& r3, uint32_t addr) {
    asm volatile("ldmatrix.sync.aligned.m8n8.x4.shared.b16 {%0,%1,%2,%3}, [%4];"
                 : "=r"(r0), "=r"(r1), "=r"(r2), "=r"(r3) : "r"(addr));
}
__device__ __forceinline__ void ldm_x2(uint32_t& r0, uint32_t& r1, uint32_t addr) {
    asm volatile("ldmatrix.sync.aligned.m8n8.x2.shared.b16 {%0,%1}, [%2];"
                 : "=r"(r0), "=r"(r1) : "r"(addr));
}
__device__ __forceinline__ uint32_t f2tf(uint32_t x) {
    uint32_t r;
    asm("cvt.rna.tf32.f32 %0, %1;" : "=r"(r) : "f"(__uint_as_float(x)));
    return r;
}
__device__ __forceinline__ float f2tff(float x) {
    uint32_t r;
    asm("cvt.rna.tf32.f32 %0, %1;" : "=r"(r) : "f"(x));
    return __uint_as_float(r);
}
__device__ __forceinline__ void mma_tf32(float* c, uint32_t a0, uint32_t a1, uint32_t a2, uint32_t a3,
                                         uint32_t b0, uint32_t b1) {
    asm volatile("mma.sync.aligned.m16n8k8.row.col.f32.tf32.tf32.f32 "
                 "{%0,%1,%2,%3}, {%4,%5,%6,%7}, {%8,%9}, {%0,%1,%2,%3};"
                 : "+f"(c[0]), "+f"(c[1]), "+f"(c[2]), "+f"(c[3])
                 : "r"(a0), "r"(a1), "r"(a2), "r"(a3), "r"(b0), "r"(b1));
}
__device__ __forceinline__ float wred_max(float v) {
#pragma unroll
    for (int o = 16; o > 0; o >>= 1) v = fmaxf(v, __shfl_xor_sync(0xffffffffu, v, o));
    return v;
}
__device__ __forceinline__ float wred_sum(float v) {
#pragma unroll
    for (int o = 16; o > 0; o >>= 1) v += __shfl_xor_sync(0xffffffffu, v, o);
    return v;
}

// ================= scratch ====================================================
__device__ float g_nx[SQ * D];          // tf32-truncated
__device__ float g_h[SQ * D];           // tf32-truncated
__device__ float g_qkv[SQ * 3 * D];     // tf32-truncated
__device__ float g_ctx[SQ * D];         // tf32-truncated
__device__ float g_mha[SQ * D];         // tf32-truncated
__device__ float g_p1[SQ * D];          // fp32
__device__ float g_n2[SQ * D];          // fp32 (residual)
__device__ float g_n2t[SQ * D];         // tf32-truncated (GEMM A)
__device__ float g_ff1[SQ * DFF];       // tf32-truncated
__device__ float g_attn_scratch[(size_t)NH * SQ * SQ];
// transposed weights [N, K], tf32-truncated
__device__ float g_wint[D * D];
__device__ float g_wqkvt[3 * D * D];
__device__ float g_wot[D * D];
__device__ float g_w2t[D * D];
__device__ float g_wf1t[DFF * D];
__device__ float g_wf2t[D * DFF];
__device__ float g_bqkv[3 * D];

// ================= weight prep: transpose + tf32 truncate ====================
__device__ __forceinline__ void wprep_tile(
    const float* __restrict__ W, float* __restrict__ T,
    int K, int N, int rowoff, int n0, int k0)
{
    __shared__ float t[32][33];
    const int tx = threadIdx.x, ty = threadIdx.y;
    for (int i = ty; i < 32; i += 8)
        t[i][tx] = W[(size_t)(k0 + i) * N + n0 + tx];
    __syncthreads();
    for (int i = ty; i < 32; i += 8)
        T[(size_t)(rowoff + n0 + i) * K + k0 + tx] = f2tff(t[tx][i]);
}

__global__ __launch_bounds__(256) void wprep_dd(
    const float* __restrict__ W_in, const float* __restrict__ Wq,
    const float* __restrict__ Wk,   const float* __restrict__ Wv,
    const float* __restrict__ Wo,   const float* __restrict__ W2,
    const float* __restrict__ bq,   const float* __restrict__ bk,
    const float* __restrict__ bv,
    float* wint, float* wqkvt, float* wot, float* w2t, float* bqkv)
{
    const int z = blockIdx.z;
    const float* W; float* T; int rowoff = 0;
    switch (z) {
        case 0:  W = W_in; T = wint;  break;
        case 1:  W = Wq;   T = wqkvt; rowoff = 0;     break;
        case 2:  W = Wk;   T = wqkvt; rowoff = D;     break;
        case 3:  W = Wv;   T = wqkvt; rowoff = 2 * D; break;
        case 4:  W = Wo;   T = wot;   break;
        default: W = W2;   T = w2t;   break;
    }
    wprep_tile(W, T, D, D, rowoff, blockIdx.x * 32, blockIdx.y * 32);
    if (z >= 1 && z <= 3 && blockIdx.x == 0 && blockIdx.y == 0) {
        const float* b = (z == 1) ? bq : (z == 2) ? bk : bv;
        for (int j = threadIdx.y * 32 + threadIdx.x; j < D; j += 256)
            bqkv[(z - 1) * D + j] = b[j];
    }
}

__global__ __launch_bounds__(256) void wprep_ff(
    const float* __restrict__ Wf1, const float* __restrict__ Wf2,
    float* f1t, float* f2t)
{
    if (blockIdx.z == 0)
        wprep_tile(Wf1, f1t, D, DFF, 0, blockIdx.x * 32, blockIdx.y * 32);
    else
        wprep_tile(Wf2, f2t, DFF, D, 0, blockIdx.y * 32, blockIdx.x * 32);
}

// ================= LayerNorm =================================================
// DUAL=0: write tf32-truncated to outt only. DUAL=1: write fp32 to outf AND tf32 to outt.
template<int DUAL>
__global__ __launch_bounds__(256) void ln_kernel(
    const float* __restrict__ x, const float* __restrict__ g,
    const float* __restrict__ b, float* __restrict__ outf, float* __restrict__ outt)
{
    __shared__ float red[8];
    __shared__ float bc[2];
    const int row = blockIdx.x;
    const int tid = threadIdx.x;
    const int lane = tid & 31, warp = tid >> 5;
    float4 v = *(const float4*)(x + (size_t)row * D + tid * 4);

    float s = wred_sum(v.x + v.y + v.z + v.w);
    if (lane == 0) red[warp] = s;
    __syncthreads();
    if (warp == 0) {
        float t = red[lane & 7];
        t += __shfl_xor_sync(0xffffffffu, t, 1);
        t += __shfl_xor_sync(0xffffffffu, t, 2);
        t += __shfl_xor_sync(0xffffffffu, t, 4);
        if (lane == 0) bc[0] = t;
    }
    __syncthreads();
    const float mean = bc[0] * (1.0f / D);
    const float dx = v.x - mean, dy = v.y - mean, dz = v.z - mean, dw = v.w - mean;

    float s2 = wred_sum(dx * dx + dy * dy + dz * dz + dw * dw);
    if (lane == 0) red[warp] = s2;
    __syncthreads();
    if (warp == 0) {
        float t = red[lane & 7];
        t += __shfl_xor_sync(0xffffffffu, t, 1);
        t += __shfl_xor_sync(0xffffffffu, t, 2);
        t += __shfl_xor_sync(0xffffffffu, t, 4);
        if (lane == 0) bc[1] = t;
    }
    __syncthreads();
    const float inv = 1.0f / (sqrtf(bc[1] * (1.0f / D)) + 1e-6f);

    float4 gg = *(const float4*)(g + tid * 4);
    float4 bb = *(const float4*)(b + tid * 4);
    float o0 = gg.x * dx * inv + bb.x;
    float o1 = gg.y * dy * inv + bb.y;
    float o2 = gg.z * dz * inv + bb.z;
    float o3 = gg.w * dw * inv + bb.w;
    const size_t base = (size_t)row * D + tid * 4;
    if (DUAL) {
        float4 o4 = {o0, o1, o2, o3};
        *(float4*)(outf + base) = o4;
    }
    float4 t4v = {f2tff(o0), f2tff(o1), f2tff(o2), f2tff(o3)};
    *(float4*)(outt + base) = t4v;
}

// ================= shared GEMM plumbing (fp32 tiles, 128B rows) ==============
__device__ __forceinline__ uint32_t swzf(int row, int g) {
    return (uint32_t)(row * 128 + ((g ^ (row & 7)) << 4));
}

template<int ROWS>
__device__ __forceinline__ void load_tf(
    const float* __restrict__ gp, int ld, int row0, int k0, uint32_t sbase, int tid)
{
#pragma unroll
    for (int it = 0; it < ROWS / 32; it++) {
        int c = tid + (it << 8);
        int row = c >> 3, g = c & 7;
        cpa16(sbase + swzf(row, g), gp + (size_t)(row0 + row) * ld + k0 + g * 4);
    }
}

// ================= TF32 GEMM (2-stage, occ 2): C = A[M,K] @ T[N,K]^T =========
// Operands are pre-truncated tf32; no inner-loop cvts.
// CVT: truncate epilogue output to tf32 (for values feeding another GEMM).
template<int BN, int RELU, int RESID, int CVT>
__global__ __launch_bounds__(256, 2) void tf_gemm(
    const float* __restrict__ A, const float* __restrict__ B,
    const float* __restrict__ bias, const float* __restrict__ res,
    float* __restrict__ C, int N, int K)
{
    constexpr int MT  = (BN == 128) ? 4 : 2;
    constexpr int SA  = 0;
    constexpr int SB  = 16384;
    constexpr int SSZ = 16384 + BN * 128;

    extern __shared__ char smem[];
    const uint32_t sb = smem_u32(smem);
    const int tid = threadIdx.x, wid = tid >> 5, lane = tid & 31;
    const int warp_m = (BN == 128) ? (wid & 1) : (wid & 3);
    const int warp_n = (BN == 128) ? (wid >> 1) : (wid >> 2);
    const int brow = blockIdx.y * 128, bcol = blockIdx.x * BN;

    float acc[MT][4][4];
#pragma unroll
    for (int a = 0; a < MT; a++)
#pragma unroll
        for (int b = 0; b < 4; b++)
#pragma unroll
            for (int c = 0; c < 4; c++) acc[a][b][c] = 0.0f;

    const int nch = K >> 5;
    load_tf<128>(A, K, brow, 0, sb + SA, tid);
    load_tf<BN>(B, K, bcol, 0, sb + SB, tid);
    CPA_COMMIT();

    const int tileA = lane >> 3;
    const int rinA  = (lane & 7) + ((tileA & 1) << 3);
    const int gA    = tileA >> 1;
    const int i16   = lane & 15;
    const int rinB  = i16 & 7;
    const int gB    = i16 >> 3;

    for (int i = 0; i < nch; i++) {
        if (i + 1 < nch) {
            const uint32_t st = sb + ((i + 1) & 1) * SSZ;
            const int k0 = (i + 1) << 5;
            load_tf<128>(A, K, brow, k0, st + SA, tid);
            load_tf<BN>(B, K, bcol, k0, st + SB, tid);
            CPA_COMMIT();
            asm volatile("cp.async.wait_group 1;" ::: "memory");
        } else {
            asm volatile("cp.async.wait_group 0;" ::: "memory");
        }
        __syncthreads();

        const uint32_t st = sb + (i & 1) * SSZ;
#pragma unroll
        for (int ks = 0; ks < 4; ks++) {
            uint32_t b0[4], b1[4];
#pragma unroll
            for (int nt = 0; nt < 4; nt++) {
                const int rowb = warp_n * 32 + nt * 8 + rinB;
                ldm_x2(b0[nt], b1[nt], st + SB + swzf(rowb, 2 * ks + gB));
            }
#pragma unroll
            for (int mt = 0; mt < MT; mt++) {
                const int rowa = warp_m * (MT * 16) + mt * 16 + rinA;
                uint32_t a0, a1, a2, a3;
                ldm_x4(a0, a1, a2, a3, st + SA + swzf(rowa, 2 * ks + gA));
#pragma unroll
                for (int nt = 0; nt < 4; nt++)
                    mma_tf32(acc[mt][nt], a0, a1, a2, a3, b0[nt], b1[nt]);
            }
        }
        __syncthreads();
    }

    const int g4 = lane >> 2, t4 = lane & 3;
#pragma unroll
    for (int mt = 0; mt < MT; mt++) {
#pragma unroll
        for (int half = 0; half < 2; half++) {
            const int row = brow + warp_m * (MT * 16) + mt * 16 + g4 + half * 8;
#pragma unroll
            for (int nt = 0; nt < 4; nt++) {
                const int col = bcol + warp_n * 32 + nt * 8 + t4 * 2;
                float v0 = acc[mt][nt][half * 2 + 0] + bias[col];
                float v1 = acc[mt][nt][half * 2 + 1] + bias[col + 1];
                if (RELU) { v0 = fmaxf(v0, 0.0f); v1 = fmaxf(v1, 0.0f); }
                const size_t o = (size_t)row * N + col;
                if (RESID) { v0 += res[o]; v1 += res[o + 1]; }
                if (CVT) { v0 = f2tff(v0); v1 = f2tff(v1); }
                float2 f2 = {v0, v1};
                *(float2*)(C + o) = f2;
            }
        }
    }
}

#define GSMEM_128 (2 * (16384 + 16384))
#define GSMEM_64  (2 * (16384 + 8192))

// ================= score (TF32): S = (Q K^T)/8, causal (no cvts) =============
#define SC_SSZ (16384 + 16384)
#define SCORE_SMEM (2 * SC_SSZ)

__global__ __launch_bounds__(256, 2) void score_mma(
    const float* __restrict__ q, const float* __restrict__ k,
    float* __restrict__ attn)
{
    const int brow = blockIdx.y * 128, bcol = blockIdx.x * 128;
    if (bcol >= brow + 128) return;
    const int h = blockIdx.z;
    const float* A = q + h * DK;
    const float* B = k + h * DK;

    extern __shared__ char smem[];
    const uint32_t sb = smem_u32(smem);
    const int tid = threadIdx.x, wid = tid >> 5, lane = tid & 31;
    const int warp_m = wid & 1, warp_n = wid >> 1;

    float acc[4][4][4];
#pragma unroll
    for (int a = 0; a < 4; a++)
#pragma unroll
        for (int b = 0; b < 4; b++)
#pragma unroll
            for (int c = 0; c < 4; c++) acc[a][b][c] = 0.0f;

    load_tf<128>(A, 3 * D, brow, 0, sb, tid);
    load_tf<128>(B, 3 * D, bcol, 0, sb + 16384, tid);
    CPA_COMMIT();

    const int tileA = lane >> 3;
    const int rinA  = (lane & 7) + ((tileA & 1) << 3);
    const int gA    = tileA >> 1;
    const int i16   = lane & 15;
    const int rinB  = i16 & 7;
    const int gB    = i16 >> 3;

    for (int i = 0; i < 2; i++) {
        if (i == 0) {
            const uint32_t st = sb + SC_SSZ;
            load_tf<128>(A, 3 * D, brow, 32, st, tid);
            load_tf<128>(B, 3 * D, bcol, 32, st + 16384, tid);
            CPA_COMMIT();
            asm volatile("cp.async.wait_group 1;" ::: "memory");
        } else {
            asm volatile("cp.async.wait_group 0;" ::: "memory");
        }
        __syncthreads();

        const uint32_t st = sb + (i & 1) * SC_SSZ;
#pragma unroll
        for (int ks = 0; ks < 4; ks++) {
            uint32_t b0[4], b1[4];
#pragma unroll
            for (int nt = 0; nt < 4; nt++) {
                const int rowb = warp_n * 32 + nt * 8 + rinB;
                ldm_x2(b0[nt], b1[nt], st + 16384 + swzf(rowb, 2 * ks + gB));
            }
#pragma unroll
            for (int mt = 0; mt < 4; mt++) {
                const int rowa = warp_m * 64 + mt * 16 + rinA;
                uint32_t a0, a1, a2, a3;
                ldm_x4(a0, a1, a2, a3, st + swzf(rowa, 2 * ks + gA));
#pragma unroll
                for (int nt = 0; nt < 4; nt++)
                    mma_tf32(acc[mt][nt], a0, a1, a2, a3, b0[nt], b1[nt]);
            }
        }
        __syncthreads();
    }

    const int g4 = lane >> 2, t4 = lane & 3;
#pragma unroll
    for (int mt = 0; mt < 4; mt++) {
#pragma unroll
        for (int half = 0; half < 2; half++) {
            const int row = brow + warp_m * 64 + mt * 16 + g4 + half * 8;
            float* arow = attn + ((size_t)h * SQ + row) * SQ;
#pragma unroll
            for (int nt = 0; nt < 4; nt++) {
                const int col = bcol + warp_n * 32 + nt * 8 + t4 * 2;
                if (col <= row)     arow[col]     = acc[mt][nt][half * 2 + 0] * 0.125f;
                if (col + 1 <= row) arow[col + 1] = acc[mt][nt][half * 2 + 1] * 0.125f;
            }
        }
    }
}

// ================= softmax (fp32, vectorized fills) ==========================
__global__ __launch_bounds__(256) void softmax_kernel(float* __restrict__ attn)
{
    __shared__ float p[SQ];
    __shared__ float red[8];
    __shared__ float bc[2];
    const int i   = blockIdx.x;
    const int h   = blockIdx.y;
    const int tid = threadIdx.x;
    const int lane = tid & 31, warp = tid >> 5;
    float* row = attn + ((size_t)h * SQ + i) * SQ;

    float m = -INFINITY;
    for (int j = tid; j <= i; j += 256) { float s = row[j]; p[j] = s; m = fmaxf(m, s); }
    m = wred_max(m);
    if (lane == 0) red[warp] = m;
    __syncthreads();
    if (warp == 0) {
        float t = red[lane & 7];
        t = fmaxf(t, __shfl_xor_sync(0xffffffffu, t, 1));
        t = fmaxf(t, __shfl_xor_sync(0xffffffffu, t, 2));
        t = fmaxf(t, __shfl_xor_sync(0xffffffffu, t, 4));
        if (lane == 0) bc[0] = t;
    }
    __syncthreads();
    const float mx = bc[0];

    float sum = 0.0f;
    for (int j = tid; j <= i; j += 256) { float e = __expf(p[j] - mx); p[j] = e; sum += e; }
    sum = wred_sum(sum);
    __syncthreads();
    if (lane == 0) red[warp] = sum;
    __syncthreads();
    if (warp == 0) {
        float t = red[lane & 7];
        t += __shfl_xor_sync(0xffffffffu, t, 1);
        t += __shfl_xor_sync(0xffffffffu, t, 2);
        t += __shfl_xor_sync(0xffffffffu, t, 4);
        if (lane == 0) bc[1] = t;
    }
    __syncthreads();
    const float inv = 1.0f / bc[1];

    for (int j = tid; j <= i; j += 256) row[j] = p[j] * inv;

    const int zs = i + 1;
    const int za = (zs + 3) & ~3;
    if (tid < za - zs && zs + tid < SQ) row[zs + tid] = 0.0f;
    const float4 zf4 = {0.0f, 0.0f, 0.0f, 0.0f};
    for (int j = za + tid * 4; j < SQ; j += 1024) *(float4*)(row + j) = zf4;
}

// ================= AV (TF32): ctx = P @ V ====================================
// A = attn fp32 (cvt in-loop, only place left); V pre-truncated.
#define AV_A   0
#define AV_B   16384
#define AV_SSZ (16384 + 32 * 72 * 4)
#define AV_SMEM (2 * AV_SSZ)

__global__ __launch_bounds__(256, 2) void av_mma(
    const float* __restrict__ attn, const float* __restrict__ v,
    float* __restrict__ ctx)
{
    const int brow = blockIdx.x * 128;
    const int h    = blockIdx.y;
    const float* A = attn + (size_t)h * SQ * SQ;
    const float* V = v + 2 * D + h * DK;

    extern __shared__ char smem[];
    const uint32_t sb = smem_u32(smem);
    float* fsm = (float*)smem;
    const int tid = threadIdx.x, wid = tid >> 5, lane = tid & 31;
    const int warp_m = wid & 3;
    const int warp_n = wid >> 2;

    float acc[2][4][4];
#pragma unroll
    for (int a = 0; a < 2; a++)
#pragma unroll
        for (int b = 0; b < 4; b++)
#pragma unroll
            for (int c = 0; c < 4; c++) acc[a][b][c] = 0.0f;

    auto load_stage = [&](int ci, uint32_t st) {
        const int k0 = ci << 5;
        load_tf<128>(A, SQ, brow, k0, st + AV_A, tid);
#pragma unroll
        for (int it = 0; it < 2; it++) {
            int c = tid + (it << 8);
            int r = c >> 4, g = c & 15;
            cpa16(st + AV_B + (uint32_t)(r * 288 + g * 16),
                  V + (size_t)(k0 + r) * (3 * D) + g * 4);
        }
        CPA_COMMIT();
    };

    const int nch = (brow >> 5) + 4;
    load_stage(0, sb);

    const int tileA = lane >> 3;
    const int rinA  = (lane & 7) + ((tileA & 1) << 3);
    const int gA    = tileA >> 1;
    const int g4 = lane >> 2, t4 = lane & 3;

    for (int i = 0; i < nch; i++) {
        if (i + 1 < nch) {
            load_stage(i + 1, sb + ((i + 1) & 1) * AV_SSZ);
            asm volatile("cp.async.wait_group 1;" ::: "memory");
        } else {
            asm volatile("cp.async.wait_group 0;" ::: "memory");
        }
        __syncthreads();

        const uint32_t st = sb + (i & 1) * AV_SSZ;
        const float* vs = fsm + ((i & 1) * AV_SSZ + AV_B) / 4;
#pragma unroll
        for (int ks = 0; ks < 4; ks++) {
            uint32_t b0[4], b1[4];
#pragma unroll
            for (int nt = 0; nt < 4; nt++) {
                const int nn = warp_n * 32 + nt * 8 + g4;
                const int kk = ks * 8 + t4;
                b0[nt] = __float_as_uint(vs[kk * 72 + nn]);
                b1[nt] = __float_as_uint(vs[(kk + 4) * 72 + nn]);
            }
#pragma unroll
            for (int mt = 0; mt < 2; mt++) {
                const int rowa = warp_m * 32 + mt * 16 + rinA;
                uint32_t a0, a1, a2, a3;
                ldm_x4(a0, a1, a2, a3, st + AV_A + swzf(rowa, 2 * ks + gA));
                a0 = f2tf(a0); a1 = f2tf(a1); a2 = f2tf(a2); a3 = f2tf(a3);
#pragma unroll
                for (int nt = 0; nt < 4; nt++)
                    mma_tf32(acc[mt][nt], a0, a1, a2, a3, b0[nt], b1[nt]);
            }
        }
        __syncthreads();
    }

#pragma unroll
    for (int mt = 0; mt < 2; mt++) {
#pragma unroll
        for (int half = 0; half < 2; half++) {
            const int row = brow + warp_m * 32 + mt * 16 + g4 + half * 8;
#pragma unroll
            for (int nt = 0; nt < 4; nt++) {
                const int col = h * DK + warp_n * 32 + nt * 8 + t4 * 2;
                float2 f2 = {f2tff(acc[mt][nt][half * 2 + 0]), f2tff(acc[mt][nt][half * 2 + 1])};
                *(float2*)(ctx + (size_t)row * D + col) = f2;
            }
        }
    }
}

// ================= host driver =================
struct Scratch {
    float *nx, *h, *qkv, *ctx, *mha, *p1, *n2, *n2t, *ff1, *attn;
    float *wint, *wqkvt, *wot, *w2t, *wf1t, *wf2t, *bqkv;
};

static Scratch get_scratch() {
    static Scratch s = [] {
        Scratch t;
        void* p;
        cudaGetSymbolAddress(&p, g_nx);    t.nx   = (float*)p;
        cudaGetSymbolAddress(&p, g_h);     t.h    = (float*)p;
        cudaGetSymbolAddress(&p, g_qkv);   t.qkv  = (float*)p;
        cudaGetSymbolAddress(&p, g_ctx);   t.ctx  = (float*)p;
        cudaGetSymbolAddress(&p, g_mha);   t.mha  = (float*)p;
        cudaGetSymbolAddress(&p, g_p1);    t.p1   = (float*)p;
        cudaGetSymbolAddress(&p, g_n2);    t.n2   = (float*)p;
        cudaGetSymbolAddress(&p, g_n2t);   t.n2t  = (float*)p;
        cudaGetSymbolAddress(&p, g_ff1);   t.ff1  = (float*)p;
        cudaGetSymbolAddress(&p, g_attn_scratch); t.attn = (float*)p;
        cudaGetSymbolAddress(&p, g_wint);  t.wint  = (float*)p;
        cudaGetSymbolAddress(&p, g_wqkvt); t.wqkvt = (float*)p;
        cudaGetSymbolAddress(&p, g_wot);   t.wot   = (float*)p;
        cudaGetSymbolAddress(&p, g_w2t);   t.w2t   = (float*)p;
        cudaGetSymbolAddress(&p, g_wf1t);  t.wf1t  = (float*)p;
        cudaGetSymbolAddress(&p, g_wf2t);  t.wf2t  = (float*)p;
        cudaGetSymbolAddress(&p, g_bqkv);  t.bqkv  = (float*)p;
        cudaFuncSetAttribute((const void*)tf_gemm<64,0,0,1>,  cudaFuncAttributeMaxDynamicSharedMemorySize, GSMEM_64);
        cudaFuncSetAttribute((const void*)tf_gemm<64,0,1,0>,  cudaFuncAttributeMaxDynamicSharedMemorySize, GSMEM_64);
        cudaFuncSetAttribute((const void*)tf_gemm<128,0,0,1>, cudaFuncAttributeMaxDynamicSharedMemorySize, GSMEM_128);
        cudaFuncSetAttribute((const void*)tf_gemm<128,1,0,1>, cudaFuncAttributeMaxDynamicSharedMemorySize, GSMEM_128);
        cudaFuncSetAttribute((const void*)score_mma, cudaFuncAttributeMaxDynamicSharedMemorySize, SCORE_SMEM);
        cudaFuncSetAttribute((const void*)av_mma,    cudaFuncAttributeMaxDynamicSharedMemorySize, AV_SMEM);
        return t;
    }();
    return s;
}

extern "C" void kernel_launch(void* const* d_in, const int* in_sizes, int n_in,
                              void* d_out, int out_size)
{
    const float* x     = (const float*)d_in[0];
    const float* g1    = (const float*)d_in[1];
    const float* beta1 = (const float*)d_in[2];
    const float* W_in  = (const float*)d_in[3];
    const float* b_in  = (const float*)d_in[4];
    const float* Wq    = (const float*)d_in[5];
    const float* bq    = (const float*)d_in[6];
    const float* Wk    = (const float*)d_in[7];
    const float* bk    = (const float*)d_in[8];
    const float* Wv    = (const float*)d_in[9];
    const float* bv    = (const float*)d_in[10];
    const float* Wo    = (const float*)d_in[11];
    const float* bo    = (const float*)d_in[12];
    const float* W2    = (const float*)d_in[13];
    const float* b2    = (const float*)d_in[14];
    const float* g2    = (const float*)d_in[15];
    const float* beta2 = (const float*)d_in[16];
    const float* Wf1   = (const float*)d_in[17];
    const float* bf1   = (const float*)d_in[18];
    const float* Wf2   = (const float*)d_in[19];
    const float* bf2   = (const float*)d_in[20];

    Scratch s = get_scratch();

    float* out  = (float*)d_out;
    const long long full = (long long)SQ * D + (long long)NH * SQ * SQ;
    float* attn = ((long long)out_size >= full) ? (out + (size_t)SQ * D) : s.attn;

    dim3 blk(256);
    dim3 wblk(32, 8);

    // #1/#2: weight prep (transpose + tf32 truncate)
    wprep_dd<<<dim3(32, 32, 6), wblk>>>(
        W_in, Wq, Wk, Wv, Wo, W2, bq, bk, bv,
        s.wint, s.wqkvt, s.wot, s.w2t, s.bqkv);
    wprep_ff<<<dim3(128, 32, 2), wblk>>>(Wf1, Wf2, s.wf1t, s.wf2t);

    // #3: LN1 -> tf32 only
    ln_kernel<0><<<SQ, blk>>>(x, g1, beta1, nullptr, s.nx);
    // #4: h = nx @ W_in + b_in  -> tf32
    tf_gemm<64,0,0,1><<<dim3(D/64, SQ/128), 256, GSMEM_64>>>(
        s.nx, s.wint, b_in, nullptr, s.h, D, D);
    // #5: qkv packed -> tf32
    tf_gemm<128,0,0,1><<<dim3(3*D/128, SQ/128), 256, GSMEM_128>>>(
        s.h, s.wqkvt, s.bqkv, nullptr, s.qkv, 3*D, D);
    // #6: scores  [ncu -s 5 captures this]
    score_mma<<<dim3(SQ/128, SQ/128, NH), 256, SCORE_SMEM>>>(
        s.qkv, s.qkv + D, attn);
    // #7: softmax (fp32 — attn is a checked output)
    softmax_kernel<<<dim3(SQ, NH), blk>>>(attn);
    // #8: AV -> ctx tf32
    av_mma<<<dim3(SQ/128, NH), 256, AV_SMEM>>>(attn, s.qkv, s.ctx);
    // #9: mha = ctx @ Wo + bo -> tf32
    tf_gemm<64,0,0,1><<<dim3(D/64, SQ/128), 256, GSMEM_64>>>(
        s.ctx, s.wot, bo, nullptr, s.mha, D, D);
    // #10: p1 = x + mha @ W2 + b2 -> fp32 (feeds LN2 only)
    tf_gemm<64,0,1,0><<<dim3(D/64, SQ/128), 256, GSMEM_64>>>(
        s.mha, s.w2t, b2, x, s.p1, D, D);
    // #11: LN2 -> fp32 (residual) + tf32 (GEMM A)
    ln_kernel<1><<<SQ, blk>>>(s.p1, g2, beta2, s.n2, s.n2t);
    // #12: ff1 = relu(n2t @ Wf1 + bf1) -> tf32
    tf_gemm<128,1,0,1><<<dim3(DFF/128, SQ/128), 256, GSMEM_128>>>(
        s.n2t, s.wf1t, bf1, nullptr, s.ff1, DFF, D);
    // #13: out = n2 + ff1 @ Wf2 + bf2 -> fp32 final
    tf_gemm<64,0,1,0><<<dim3(D/64, SQ/128), 256, GSMEM_64>>>(
        s.ff1, s.wf2t, bf2, s.n2, out, D, DFF);
}